// round 8
// baseline (speedup 1.0000x reference)
#include <cuda_runtime.h>
#include <cstddef>

#define BATCH   4
#define CIN     1024
#define HH      64
#define WW      64
#define NPIX    4096            // 64*64
#define PLANES  256
#define KTAPS   9
#define EPSV    1e-5f

// ---------------- scratch (device globals: allocation-guard safe) ----------------
__device__ float g_out1[(size_t)BATCH * PLANES * NPIX];          // 16 MB
__device__ float g_off [(size_t)BATCH * 18 * NPIX];              // 1.2 MB
__device__ float g_cols[(size_t)BATCH * PLANES * KTAPS * NPIX];  // 151 MB
__device__ float g_out2[(size_t)BATCH * PLANES * NPIX];          // 16 MB

// ---------------- generic SGEMM with fused epilogues ----------------
// C[M,N] = A[M,K] (row-major, shared across batch) * B[K,N] (row-major, per-batch)
// EPI 1: relu(BN(acc))                 -> conv1
// EPI 2: relu(BN(acc + bias[m]))       -> deform conv
// EPI 3: relu(BN(acc) + resid[m,n])    -> conv3 (+ residual)
template<int EPI>
__global__ __launch_bounds__(256)
void sgemm_kernel(const float* __restrict__ A,
                  const float* __restrict__ Bm,
                  float* __restrict__ C,
                  int M, int N, int K,
                  long strideB, long strideC,
                  const float* __restrict__ bias,
                  const float* __restrict__ gamma,
                  const float* __restrict__ beta,
                  const float* __restrict__ mean,
                  const float* __restrict__ var,
                  const float* __restrict__ resid,
                  long strideRes)
{
    const int bx = blockIdx.x;   // N tile
    const int by = blockIdx.y;   // M tile
    const int bz = blockIdx.z;   // batch
    Bm += (size_t)bz * strideB;
    C  += (size_t)bz * strideC;

    __shared__ float As[16][128];
    __shared__ float Bs[16][128];

    const int tid = threadIdx.x;
    const int tx  = tid & 15;     // 0..15 -> N micro tile
    const int ty  = tid >> 4;     // 0..15 -> M micro tile

    // A tile loader mapping: 128 rows x 16 cols, 8 floats/thread (2x float4)
    const int aRow = tid >> 2;          // 0..63
    const int aCol = (tid & 3) * 4;     // 0,4,8,12
    // B tile loader mapping: 16 rows x 128 cols
    const int bRow = tid >> 5;          // 0..7
    const int bCol = (tid & 31) * 4;

    const float* Ab = A  + (size_t)(by * 128) * K;
    const float* Bb = Bm + (size_t)(bx * 128);

    float acc[8][8];
    #pragma unroll
    for (int i = 0; i < 8; i++)
        #pragma unroll
        for (int j = 0; j < 8; j++) acc[i][j] = 0.f;

    for (int kt = 0; kt < K; kt += 16) {
        float4 a0 = *(const float4*)(Ab + (size_t)aRow        * K + kt + aCol);
        float4 a1 = *(const float4*)(Ab + (size_t)(aRow + 64) * K + kt + aCol);
        As[aCol + 0][aRow] = a0.x;  As[aCol + 1][aRow] = a0.y;
        As[aCol + 2][aRow] = a0.z;  As[aCol + 3][aRow] = a0.w;
        As[aCol + 0][aRow + 64] = a1.x;  As[aCol + 1][aRow + 64] = a1.y;
        As[aCol + 2][aRow + 64] = a1.z;  As[aCol + 3][aRow + 64] = a1.w;

        float4 b0 = *(const float4*)(Bb + (size_t)(kt + bRow)     * N + bCol);
        float4 b1 = *(const float4*)(Bb + (size_t)(kt + bRow + 8) * N + bCol);
        *(float4*)&Bs[bRow][bCol]     = b0;
        *(float4*)&Bs[bRow + 8][bCol] = b1;

        __syncthreads();

        #pragma unroll
        for (int k = 0; k < 16; k++) {
            float ar[8], br[8];
            *(float4*)&ar[0] = *(const float4*)&As[k][ty * 8];
            *(float4*)&ar[4] = *(const float4*)&As[k][ty * 8 + 4];
            *(float4*)&br[0] = *(const float4*)&Bs[k][tx * 8];
            *(float4*)&br[4] = *(const float4*)&Bs[k][tx * 8 + 4];
            #pragma unroll
            for (int i = 0; i < 8; i++)
                #pragma unroll
                for (int j = 0; j < 8; j++)
                    acc[i][j] += ar[i] * br[j];
        }
        __syncthreads();
    }

    #pragma unroll
    for (int i = 0; i < 8; i++) {
        const int m = by * 128 + ty * 8 + i;
        const float inv = rsqrtf(var[m] + EPSV);
        const float sc  = inv * gamma[m];
        const float sh  = beta[m] - mean[m] * sc;
        float bi = 0.f;
        if (EPI == 2) bi = bias[m];
        #pragma unroll
        for (int j = 0; j < 8; j++) {
            const int n = bx * 128 + tx * 8 + j;
            float v = acc[i][j];
            if (EPI == 2) v += bi;
            v = v * sc + sh;
            if (EPI == 3) v += resid[(size_t)bz * strideRes + (size_t)m * N + n];
            v = fmaxf(v, 0.f);
            C[(size_t)m * N + n] = v;
        }
    }
}

// ---------------- offset predictor: dilated 3x3 conv, 256 -> 18 ----------------
__global__ __launch_bounds__(128)
void offset_conv_kernel(const float* __restrict__ out1,
                        const float* __restrict__ woff,   // [18][256][3][3]
                        const float* __restrict__ boff,   // [18]
                        float* __restrict__ off)          // [B][18][64][64]
{
    const int idx = blockIdx.x * 128 + threadIdx.x;       // 0..16383
    const int b = idx >> 12;
    const int p = idx & 4095;
    const int h = p >> 6, w = p & 63;

    float acc[18];
    #pragma unroll
    for (int o = 0; o < 18; o++) acc[o] = 0.f;

    const float* base = out1 + (size_t)b * PLANES * NPIX;
    for (int c = 0; c < PLANES; c++) {
        const float* pl = base + (size_t)c * NPIX;
        float v[9];
        #pragma unroll
        for (int k = 0; k < 9; k++) {
            const int yy = h + (k / 3) * 2 - 2;
            const int xx = w + (k % 3) * 2 - 2;
            v[k] = (yy >= 0 && yy < HH && xx >= 0 && xx < WW) ? pl[yy * WW + xx] : 0.f;
        }
        #pragma unroll
        for (int k = 0; k < 9; k++) {
            #pragma unroll
            for (int o = 0; o < 18; o++)
                acc[o] += v[k] * woff[((size_t)o * PLANES + c) * 9 + k];
        }
    }
    #pragma unroll
    for (int o = 0; o < 18; o++)
        off[((size_t)b * 18 + o) * NPIX + p] = acc[o] + boff[o];
}

// ---------------- deformable im2col (bilinear gather) ----------------
// cols[b][(c*9+k)][p] = bilinear(out1[b][c], coords(b,k,p))
__global__ __launch_bounds__(256)
void deform_im2col_kernel(const float* __restrict__ out1,
                          const float* __restrict__ off,
                          float* __restrict__ cols)
{
    const int p = blockIdx.x * 256 + threadIdx.x;   // 0..4095
    const int k = blockIdx.y;                       // 0..8
    const int b = blockIdx.z;                       // 0..3
    const int h = p >> 6, w = p & 63;

    const float oy = off[((size_t)b * 18 + 2 * k)     * NPIX + p];
    const float ox = off[((size_t)b * 18 + 2 * k + 1) * NPIX + p];
    const float py = (float)((k / 3) * 2 - 2 + h) + oy;
    const float px = (float)((k % 3) * 2 - 2 + w) + ox;

    const float y0f = floorf(py), x0f = floorf(px);
    const float wy = py - y0f, wx = px - x0f;
    const int y0 = (int)y0f, x0 = (int)x0f;
    const int y1 = y0 + 1,   x1 = x0 + 1;

    const float vy0 = (y0 >= 0 && y0 < HH) ? 1.f : 0.f;
    const float vy1 = (y1 >= 0 && y1 < HH) ? 1.f : 0.f;
    const float vx0 = (x0 >= 0 && x0 < WW) ? 1.f : 0.f;
    const float vx1 = (x1 >= 0 && x1 < WW) ? 1.f : 0.f;

    const int cy0 = min(max(y0, 0), HH - 1), cy1 = min(max(y1, 0), HH - 1);
    const int cx0 = min(max(x0, 0), WW - 1), cx1 = min(max(x1, 0), WW - 1);

    const float w00 = (1.f - wy) * (1.f - wx) * vy0 * vx0;
    const float w01 = (1.f - wy) * wx         * vy0 * vx1;
    const float w10 = wy         * (1.f - wx) * vy1 * vx0;
    const float w11 = wy         * wx         * vy1 * vx1;

    const int i00 = cy0 * WW + cx0, i01 = cy0 * WW + cx1;
    const int i10 = cy1 * WW + cx0, i11 = cy1 * WW + cx1;

    const float* base  = out1 + (size_t)b * PLANES * NPIX;
    float*       cbase = cols + (size_t)b * PLANES * KTAPS * NPIX + (size_t)k * NPIX + p;

    #pragma unroll 4
    for (int c = 0; c < PLANES; c++) {
        const float* pl = base + (size_t)c * NPIX;
        const float v = w00 * pl[i00] + w01 * pl[i01] + w10 * pl[i10] + w11 * pl[i11];
        cbase[(size_t)c * KTAPS * NPIX] = v;
    }
}

// ---------------- launch ----------------
extern "C" void kernel_launch(void* const* d_in, const int* in_sizes, int n_in,
                              void* d_out, int out_size)
{
    const float* x      = (const float*)d_in[0];   // [4,1024,64,64]
    const float* w1     = (const float*)d_in[1];   // [256,1024]
    const float* gamma1 = (const float*)d_in[2];
    const float* beta1  = (const float*)d_in[3];
    const float* mean1  = (const float*)d_in[4];
    const float* var1   = (const float*)d_in[5];
    const float* woff   = (const float*)d_in[6];   // [18,256,3,3]
    const float* boff   = (const float*)d_in[7];   // [18]
    const float* w2     = (const float*)d_in[8];   // [256,256,3,3]
    const float* bconv2 = (const float*)d_in[9];
    const float* gamma2 = (const float*)d_in[10];
    const float* beta2  = (const float*)d_in[11];
    const float* mean2  = (const float*)d_in[12];
    const float* var2   = (const float*)d_in[13];
    const float* w3     = (const float*)d_in[14];  // [1024,256]
    const float* gamma3 = (const float*)d_in[15];
    const float* beta3  = (const float*)d_in[16];
    const float* mean3  = (const float*)d_in[17];
    const float* var3   = (const float*)d_in[18];
    float* out = (float*)d_out;

    float *p_out1, *p_off, *p_cols, *p_out2;
    cudaGetSymbolAddress((void**)&p_out1, g_out1);
    cudaGetSymbolAddress((void**)&p_off,  g_off);
    cudaGetSymbolAddress((void**)&p_cols, g_cols);
    cudaGetSymbolAddress((void**)&p_out2, g_out2);

    // 1) conv1 (1x1) + BN1 + ReLU : [256x1024] x [1024x4096] per batch
    sgemm_kernel<1><<<dim3(NPIX / 128, PLANES / 128, BATCH), 256>>>(
        w1, x, p_out1, PLANES, NPIX, CIN,
        (long)CIN * NPIX, (long)PLANES * NPIX,
        nullptr, gamma1, beta1, mean1, var1, nullptr, 0);

    // 2) offset predictor (dilated 3x3, 256 -> 18)
    offset_conv_kernel<<<(BATCH * NPIX) / 128, 128>>>(p_out1, woff, boff, p_off);

    // 3) deformable im2col
    deform_im2col_kernel<<<dim3(NPIX / 256, KTAPS, BATCH), 256>>>(p_out1, p_off, p_cols);

    // 4) deform GEMM + bias + BN2 + ReLU : [256x2304] x [2304x4096] per batch
    sgemm_kernel<2><<<dim3(NPIX / 128, PLANES / 128, BATCH), 256>>>(
        w2, p_cols, p_out2, PLANES, NPIX, PLANES * KTAPS,
        (long)PLANES * KTAPS * NPIX, (long)PLANES * NPIX,
        bconv2, gamma2, beta2, mean2, var2, nullptr, 0);

    // 5) conv3 (1x1) + BN3 + residual + ReLU : [1024x256] x [256x4096] per batch
    sgemm_kernel<3><<<dim3(NPIX / 128, CIN / 128, BATCH), 256>>>(
        w3, p_out2, out, CIN, NPIX, PLANES,
        (long)PLANES * NPIX, (long)CIN * NPIX,
        nullptr, gamma3, beta3, mean3, var3, x, (long)CIN * NPIX);
}

// round 10
// speedup vs baseline: 1.7706x; 1.7706x over previous
#include <cuda_runtime.h>
#include <cstdint>
#include <cstddef>

#define BATCH   4
#define CIN     1024
#define NPIX    4096
#define MTOT    (BATCH * NPIX)      // 16384 pixels total
#define PLANES  256
#define EPSV    1e-5f

// ---------------- scratch (device globals: allocation-guard safe) ----------------
__device__ float g_xT       [(size_t)MTOT * CIN];          // 64 MB  x transposed [P][C]
__device__ float g_out1_nhwc[(size_t)MTOT * PLANES];       // 16 MB  [P][256]
__device__ float g_out1_nchw[(size_t)MTOT * PLANES];       // 16 MB  [b][256][4096]
__device__ float g_off      [(size_t)BATCH * 18 * NPIX];   // 1.2 MB
__device__ float g_cols     [(size_t)MTOT * PLANES * 9];   // 151 MB [P][k*256+c]
__device__ float g_out2     [(size_t)MTOT * PLANES];       // 16 MB  [P][256]
__device__ float g_w2r      [(size_t)PLANES * PLANES * 9]; // 2.3 MB [o][k*256+c]

// ---------------- helpers ----------------
__device__ __forceinline__ uint32_t f2tf(float f) {   // round-to-nearest tf32
    uint32_t u;
    asm("cvt.rna.tf32.f32 %0, %1;" : "=r"(u) : "f"(f));
    return u;
}
__device__ __forceinline__ void mma_tf32(float* c, const uint32_t* a, const uint32_t* b) {
    asm volatile(
        "mma.sync.aligned.m16n8k8.row.col.f32.tf32.tf32.f32 "
        "{%0,%1,%2,%3}, {%4,%5,%6,%7}, {%8,%9}, {%0,%1,%2,%3};"
        : "+f"(c[0]), "+f"(c[1]), "+f"(c[2]), "+f"(c[3])
        : "r"(a[0]), "r"(a[1]), "r"(a[2]), "r"(a[3]), "r"(b[0]), "r"(b[1]));
}

// ======================= tf32 mma.sync GEMM =======================
// D[P, n] = sum_k A[P, k] * B[n, k]
// CTA tile 128x128, BK=32, 8 warps (2 M x 4 N), warp tile 64x32.
// EPI 1: relu(BN(acc))          -> NHWC + NCHW   (conv1)
// EPI 2: relu(BN(acc + bias))   -> NHWC          (deform conv)
// EPI 3: relu(BN(acc) + resid)  -> NCHW          (conv3, Cout=1024)
#define BM 128
#define BN 128
#define BK 32
#define ASTR 36                  // padded K-stride for A/B smem tiles
#define CSTR 133                 // padded N-stride for C staging (133 % 32 = 5, coprime)

// smem layout (float offsets)
#define OFF_SCALE 0
#define OFF_SHIFT 128
#define OFF_A     256
#define OFF_B     (OFF_A + BM * ASTR)      // 256 + 4608
#define OFF_C     (OFF_B + BN * ASTR)      // + 4608
#define SM_FLOATS (OFF_C + BM * CSTR)      // + 17024 = 26496 floats
#define SM_BYTES  (SM_FLOATS * 4)          // 105984 bytes

template<int EPI>
__global__ __launch_bounds__(256)
void gemm_mma(const float* __restrict__ A, const float* __restrict__ Bw,
              int Kdim,
              float* __restrict__ outNHWC, float* __restrict__ outNCHW,
              const float* __restrict__ bias,
              const float* __restrict__ gamma, const float* __restrict__ beta,
              const float* __restrict__ mean, const float* __restrict__ var,
              const float* __restrict__ resid, int Cout)
{
    extern __shared__ float sm[];
    float* s_scale = sm + OFF_SCALE;
    float* s_shift = sm + OFF_SHIFT;
    float* As = sm + OFF_A;
    float* Bs = sm + OFF_B;
    float* Cs = sm + OFF_C;

    const int tid = threadIdx.x;
    const int wid = tid >> 5, lane = tid & 31;
    const int lr = lane >> 2, lc = lane & 3;
    const int mt = blockIdx.x, nt = blockIdx.y;
    const int wm = (wid & 1) * 64, wn = (wid >> 1) * 32;

    if (tid < BN) {   // per-column BN scale/shift (bias folded for EPI 2)
        const int n = nt * BN + tid;
        const float inv = rsqrtf(var[n] + EPSV);
        const float sc = inv * gamma[n];
        float sh = beta[n] - mean[n] * sc;
        if (EPI == 2) sh += bias[n] * sc;
        s_scale[tid] = sc;
        s_shift[tid] = sh;
    }

    float c[4][4][4];
    #pragma unroll
    for (int mi = 0; mi < 4; mi++)
        #pragma unroll
        for (int ni = 0; ni < 4; ni++)
            #pragma unroll
            for (int j = 0; j < 4; j++) c[mi][ni][j] = 0.f;

    const float* Ab = A  + (size_t)(mt * BM) * Kdim;
    const float* Bb = Bw + (size_t)(nt * BN) * Kdim;
    const uint32_t* As32 = (const uint32_t*)As;
    const uint32_t* Bs32 = (const uint32_t*)Bs;

    for (int kc = 0; kc < Kdim; kc += BK) {
        __syncthreads();   // prior reads of As/Bs complete before overwrite
        #pragma unroll
        for (int i = 0; i < 4; i++) {      // 128 rows x 32 K, float4 units
            const int u = tid + i * 256, r = u >> 3, q = u & 7;
            float4 va = *(const float4*)(Ab + (size_t)r * Kdim + kc + q * 4);
            uint4 ua; ua.x = f2tf(va.x); ua.y = f2tf(va.y); ua.z = f2tf(va.z); ua.w = f2tf(va.w);
            *(uint4*)(As + r * ASTR + q * 4) = ua;
            float4 vb = *(const float4*)(Bb + (size_t)r * Kdim + kc + q * 4);
            uint4 ub; ub.x = f2tf(vb.x); ub.y = f2tf(vb.y); ub.z = f2tf(vb.z); ub.w = f2tf(vb.w);
            *(uint4*)(Bs + r * ASTR + q * 4) = ub;
        }
        __syncthreads();

        #pragma unroll
        for (int kk = 0; kk < BK; kk += 8) {
            uint32_t af[4][4], bf[4][2];
            #pragma unroll
            for (int t = 0; t < 4; t++) {              // A frags: rows wm+t*16
                const int m0 = wm + t * 16;
                af[t][0] = As32[(m0 + lr)     * ASTR + kk + lc];
                af[t][1] = As32[(m0 + lr + 8) * ASTR + kk + lc];
                af[t][2] = As32[(m0 + lr)     * ASTR + kk + lc + 4];
                af[t][3] = As32[(m0 + lr + 8) * ASTR + kk + lc + 4];
            }
            #pragma unroll
            for (int t = 0; t < 4; t++) {              // B frags: cols wn+t*8
                const int n0 = wn + t * 8;
                bf[t][0] = Bs32[(n0 + lr) * ASTR + kk + lc];
                bf[t][1] = Bs32[(n0 + lr) * ASTR + kk + lc + 4];
            }
            #pragma unroll
            for (int mi = 0; mi < 4; mi++)
                #pragma unroll
                for (int ni = 0; ni < 4; ni++)
                    mma_tf32(c[mi][ni], af[mi], bf[ni]);
        }
    }

    __syncthreads();
    // dump accumulators to padded C staging tile
    #pragma unroll
    for (int mi = 0; mi < 4; mi++) {
        #pragma unroll
        for (int ni = 0; ni < 4; ni++) {
            const int m0 = wm + mi * 16, n0 = wn + ni * 8;
            Cs[(m0 + lr)     * CSTR + n0 + 2 * lc]     = c[mi][ni][0];
            Cs[(m0 + lr)     * CSTR + n0 + 2 * lc + 1] = c[mi][ni][1];
            Cs[(m0 + lr + 8) * CSTR + n0 + 2 * lc]     = c[mi][ni][2];
            Cs[(m0 + lr + 8) * CSTR + n0 + 2 * lc + 1] = c[mi][ni][3];
        }
    }
    __syncthreads();

    const int P0 = mt * BM, b = P0 >> 12, p0 = P0 & 4095;
    if (EPI != 3) {
        // NHWC stream-out: n contiguous across threads (coalesced)
        #pragma unroll
        for (int i = 0; i < 64; i++) {
            const int n = tid & 127;
            const int p = i * 2 + (tid >> 7);
            const float v = fmaxf(Cs[p * CSTR + n] * s_scale[n] + s_shift[n], 0.f);
            outNHWC[(size_t)(P0 + p) * PLANES + nt * BN + n] = v;
        }
    }
    if (EPI == 1 || EPI == 3) {
        // NCHW stream-out: p contiguous across threads (coalesced)
        #pragma unroll
        for (int i = 0; i < 64; i++) {
            const int n = i * 2 + (tid >> 7);
            const int p = tid & 127;
            float v = Cs[p * CSTR + n] * s_scale[n] + s_shift[n];
            const size_t o = ((size_t)b * Cout + nt * BN + n) * NPIX + p0 + p;
            if (EPI == 3) v += resid[o];
            outNCHW[o] = fmaxf(v, 0.f);
        }
    }
}

// ======================= transpose x: [b][1024][4096] -> xT [b*4096+p][1024] =======================
__global__ __launch_bounds__(256)
void transpose_k(const float* __restrict__ x, float* __restrict__ xT)
{
    __shared__ float t[32][33];
    const int b = blockIdx.z;
    const int p0 = blockIdx.x * 32, c0 = blockIdx.y * 32;
    const float* in = x + (size_t)b * CIN * NPIX;
    float* out = xT + (size_t)b * NPIX * CIN;
    const int tx = threadIdx.x & 31, ty = threadIdx.x >> 5;   // 32 x 8
    #pragma unroll
    for (int i = 0; i < 32; i += 8)
        t[ty + i][tx] = in[(size_t)(c0 + ty + i) * NPIX + p0 + tx];
    __syncthreads();
    #pragma unroll
    for (int i = 0; i < 32; i += 8)
        out[(size_t)(p0 + ty + i) * CIN + c0 + tx] = t[tx][ty + i];
}

// ======================= w2 reshuffle: [o][c][k] -> [o][k*256+c] =======================
__global__ __launch_bounds__(256)
void w2r_k(const float* __restrict__ w2, float* __restrict__ w2r)
{
    const int idx = blockIdx.x * 256 + threadIdx.x;   // 256*2304 total
    const int o = idx / 2304, rr = idx % 2304;
    const int k = rr >> 8, cc = rr & 255;
    w2r[idx] = w2[((size_t)o * 256 + cc) * 9 + k];
}

// ======================= offset predictor (NCHW, broadcast-weight; validated R3) =======================
__global__ __launch_bounds__(128)
void offset_conv_kernel(const float* __restrict__ out1,
                        const float* __restrict__ woff,
                        const float* __restrict__ boff,
                        float* __restrict__ off)
{
    const int idx = blockIdx.x * 128 + threadIdx.x;
    const int b = idx >> 12;
    const int p = idx & 4095;
    const int h = p >> 6, w = p & 63;

    float acc[18];
    #pragma unroll
    for (int o = 0; o < 18; o++) acc[o] = 0.f;

    const float* base = out1 + (size_t)b * PLANES * NPIX;
    for (int cc = 0; cc < PLANES; cc++) {
        const float* pl = base + (size_t)cc * NPIX;
        float v[9];
        #pragma unroll
        for (int k = 0; k < 9; k++) {
            const int yy = h + (k / 3) * 2 - 2;
            const int xx = w + (k % 3) * 2 - 2;
            v[k] = (yy >= 0 && yy < 64 && xx >= 0 && xx < 64) ? pl[yy * 64 + xx] : 0.f;
        }
        #pragma unroll
        for (int k = 0; k < 9; k++) {
            #pragma unroll
            for (int o = 0; o < 18; o++)
                acc[o] += v[k] * woff[((size_t)o * PLANES + cc) * 9 + k];
        }
    }
    #pragma unroll
    for (int o = 0; o < 18; o++)
        off[((size_t)b * 18 + o) * NPIX + p] = acc[o] + boff[o];
}

// ======================= deformable im2col, NHWC (warp per pixel-tap) =======================
__global__ __launch_bounds__(256)
void im2col_k(const float* __restrict__ out1,   // NHWC [16384][256]
              const float* __restrict__ off,
              float* __restrict__ cols)         // [P][k*256+c]
{
    const int gw = blockIdx.x * 8 + (threadIdx.x >> 5);   // 147456 total
    const int lane = threadIdx.x & 31;
    const int k = gw % 9;
    const int P = gw / 9;
    const int b = P >> 12, p = P & 4095, h = p >> 6, w = p & 63;

    const float oy = off[((size_t)b * 18 + 2 * k)     * NPIX + p];
    const float ox = off[((size_t)b * 18 + 2 * k + 1) * NPIX + p];
    const float py = (float)((k / 3) * 2 - 2 + h) + oy;
    const float px = (float)((k % 3) * 2 - 2 + w) + ox;

    const float y0f = floorf(py), x0f = floorf(px);
    const float wy = py - y0f, wx = px - x0f;
    const int y0 = (int)y0f, x0 = (int)x0f, y1 = y0 + 1, x1 = x0 + 1;
    const float vy0 = (y0 >= 0 && y0 < 64) ? 1.f : 0.f;
    const float vy1 = (y1 >= 0 && y1 < 64) ? 1.f : 0.f;
    const float vx0 = (x0 >= 0 && x0 < 64) ? 1.f : 0.f;
    const float vx1 = (x1 >= 0 && x1 < 64) ? 1.f : 0.f;
    const int cy0 = min(max(y0, 0), 63), cy1 = min(max(y1, 0), 63);
    const int cx0 = min(max(x0, 0), 63), cx1 = min(max(x1, 0), 63);
    const float w00 = (1.f - wy) * (1.f - wx) * vy0 * vx0;
    const float w01 = (1.f - wy) * wx         * vy0 * vx1;
    const float w10 = wy         * (1.f - wx) * vy1 * vx0;
    const float w11 = wy         * wx         * vy1 * vx1;

    const size_t rb = (size_t)(b << 12);
    const float* r00 = out1 + (rb + cy0 * 64 + cx0) * PLANES;
    const float* r01 = out1 + (rb + cy0 * 64 + cx1) * PLANES;
    const float* r10 = out1 + (rb + cy1 * 64 + cx0) * PLANES;
    const float* r11 = out1 + (rb + cy1 * 64 + cx1) * PLANES;
    float* dst = cols + (size_t)P * (PLANES * 9) + k * PLANES;

    const int c0 = lane * 8;
    #pragma unroll
    for (int q = 0; q < 2; q++) {
        const int cidx = c0 + q * 4;
        const float4 a  = *(const float4*)(r00 + cidx);
        const float4 bq = *(const float4*)(r01 + cidx);
        const float4 cq = *(const float4*)(r10 + cidx);
        const float4 dq = *(const float4*)(r11 + cidx);
        float4 v;
        v.x = w00 * a.x + w01 * bq.x + w10 * cq.x + w11 * dq.x;
        v.y = w00 * a.y + w01 * bq.y + w10 * cq.y + w11 * dq.y;
        v.z = w00 * a.z + w01 * bq.z + w10 * cq.z + w11 * dq.z;
        v.w = w00 * a.w + w01 * bq.w + w10 * cq.w + w11 * dq.w;
        *(float4*)(dst + cidx) = v;
    }
}

// ======================= launch =======================
extern "C" void kernel_launch(void* const* d_in, const int* in_sizes, int n_in,
                              void* d_out, int out_size)
{
    const float* x      = (const float*)d_in[0];
    const float* w1     = (const float*)d_in[1];
    const float* gamma1 = (const float*)d_in[2];
    const float* beta1  = (const float*)d_in[3];
    const float* mean1  = (const float*)d_in[4];
    const float* var1   = (const float*)d_in[5];
    const float* woff   = (const float*)d_in[6];
    const float* boff   = (const float*)d_in[7];
    const float* w2     = (const float*)d_in[8];
    const float* bconv2 = (const float*)d_in[9];
    const float* gamma2 = (const float*)d_in[10];
    const float* beta2  = (const float*)d_in[11];
    const float* mean2  = (const float*)d_in[12];
    const float* var2   = (const float*)d_in[13];
    const float* w3     = (const float*)d_in[14];
    const float* gamma3 = (const float*)d_in[15];
    const float* beta3  = (const float*)d_in[16];
    const float* mean3  = (const float*)d_in[17];
    const float* var3   = (const float*)d_in[18];
    float* out = (float*)d_out;

    float *p_xT, *p_o1h, *p_o1c, *p_off, *p_cols, *p_out2, *p_w2r;
    cudaGetSymbolAddress((void**)&p_xT,   g_xT);
    cudaGetSymbolAddress((void**)&p_o1h,  g_out1_nhwc);
    cudaGetSymbolAddress((void**)&p_o1c,  g_out1_nchw);
    cudaGetSymbolAddress((void**)&p_off,  g_off);
    cudaGetSymbolAddress((void**)&p_cols, g_cols);
    cudaGetSymbolAddress((void**)&p_out2, g_out2);
    cudaGetSymbolAddress((void**)&p_w2r,  g_w2r);

    cudaFuncSetAttribute(gemm_mma<1>, cudaFuncAttributeMaxDynamicSharedMemorySize, SM_BYTES);
    cudaFuncSetAttribute(gemm_mma<2>, cudaFuncAttributeMaxDynamicSharedMemorySize, SM_BYTES);
    cudaFuncSetAttribute(gemm_mma<3>, cudaFuncAttributeMaxDynamicSharedMemorySize, SM_BYTES);

    // independent prep
    transpose_k<<<dim3(NPIX / 32, CIN / 32, BATCH), 256>>>(x, p_xT);
    w2r_k<<<2304, 256>>>(w2, p_w2r);

    // 1) conv1: [16384,1024] x [256,1024]^T -> out1 (NHWC + NCHW), BN1+ReLU
    gemm_mma<1><<<dim3(MTOT / BM, PLANES / BN), 256, SM_BYTES>>>(
        p_xT, w1, CIN, p_o1h, p_o1c, nullptr,
        gamma1, beta1, mean1, var1, nullptr, PLANES);

    // 2) offset predictor (NCHW input)
    offset_conv_kernel<<<(BATCH * NPIX) / 128, 128>>>(p_o1c, woff, boff, p_off);

    // 3) deformable im2col (NHWC)
    im2col_k<<<(MTOT * 9) / 8, 256>>>(p_o1h, p_off, p_cols);

    // 4) deform GEMM: [16384,2304] x [256,2304]^T + bias, BN2+ReLU -> out2 NHWC
    gemm_mma<2><<<dim3(MTOT / BM, PLANES / BN), 256, SM_BYTES>>>(
        p_cols, p_w2r, PLANES * 9, p_out2, nullptr, bconv2,
        gamma2, beta2, mean2, var2, nullptr, PLANES);

    // 5) conv3: [16384,256] x [1024,256]^T, BN3 + residual + ReLU -> out NCHW
    gemm_mma<3><<<dim3(MTOT / BM, CIN / BN), 256, SM_BYTES>>>(
        p_out2, w3, PLANES, nullptr, out, nullptr,
        gamma3, beta3, mean3, var3, x, CIN);
}

// round 13
// speedup vs baseline: 2.5539x; 1.4424x over previous
#include <cuda_runtime.h>
#include <cstdint>
#include <cstddef>

#define BATCH   4
#define CIN     1024
#define NPIX    4096
#define MTOT    (BATCH * NPIX)      // 16384 pixels total
#define PLANES  256
#define EPSV    1e-5f
#define CSPLIT  8                   // offset-conv channel splits

// ---------------- scratch (device globals: allocation-guard safe) ----------------
__device__ float g_xT       [(size_t)MTOT * CIN];          // 64 MB  x transposed [P][C]
__device__ float g_out1_nhwc[(size_t)MTOT * PLANES];       // 16 MB  [P][256]
__device__ float g_out1_nchw[(size_t)MTOT * PLANES];       // 16 MB  [b][256][4096]
__device__ float g_off      [(size_t)BATCH * 18 * NPIX];   // 1.2 MB
__device__ float g_offp     [(size_t)CSPLIT * BATCH * 18 * NPIX]; // 9.4 MB partials
__device__ float g_cols     [(size_t)MTOT * PLANES * 9];   // 151 MB [P][k*256+c]
__device__ float g_out2     [(size_t)MTOT * PLANES];       // 16 MB  [P][256]
__device__ float g_w2r      [(size_t)PLANES * PLANES * 9]; // 2.3 MB [o][k*256+c]

// ---------------- helpers ----------------
__device__ __forceinline__ uint32_t f2tf(float f) {   // round-to-nearest tf32
    uint32_t u;
    asm("cvt.rna.tf32.f32 %0, %1;" : "=r"(u) : "f"(f));
    return u;
}
__device__ __forceinline__ void mma_tf32(float* c, const uint32_t* a, const uint32_t* b) {
    asm volatile(
        "mma.sync.aligned.m16n8k8.row.col.f32.tf32.tf32.f32 "
        "{%0,%1,%2,%3}, {%4,%5,%6,%7}, {%8,%9}, {%0,%1,%2,%3};"
        : "+f"(c[0]), "+f"(c[1]), "+f"(c[2]), "+f"(c[3])
        : "r"(a[0]), "r"(a[1]), "r"(a[2]), "r"(a[3]), "r"(b[0]), "r"(b[1]));
}

// ======================= tf32 mma.sync GEMM =======================
// D[P, n] = sum_k A[P, k] * B[n, k]
// CTA tile 128x128, BK=32, 8 warps (2 M x 4 N), warp tile 64x32.
// grid = (NT, MT): nt on x so CTAs sharing an A tile are wave-concurrent (L2 reuse).
// EPI 1: relu(BN(acc))          -> NHWC + NCHW   (conv1)
// EPI 2: relu(BN(acc + bias))   -> NHWC          (deform conv)
// EPI 3: relu(BN(acc) + resid)  -> NCHW          (conv3, Cout=1024)
#define BM 128
#define BN 128
#define BK 32
#define ASTR 36                  // padded K-stride for A/B smem tiles
#define CSTR 133                 // padded N-stride for C staging (coprime with 32)

// smem layout (float offsets); C staging ALIASES the A/B tiles (only live post-loop)
#define OFF_SCALE 0
#define OFF_SHIFT 128
#define OFF_A     256
#define OFF_B     (OFF_A + BM * ASTR)            // 256 + 4608
#define OFF_C     OFF_A
#define SM_FLOATS (OFF_A + BM * CSTR)            // 256 + 17024 = 17280 floats
#define SM_BYTES  (SM_FLOATS * 4)                // 69120 bytes -> 2 CTAs/SM

template<int EPI>
__global__ __launch_bounds__(256, 2)
void gemm_mma(const float* __restrict__ A, const float* __restrict__ Bw,
              int Kdim,
              float* __restrict__ outNHWC, float* __restrict__ outNCHW,
              const float* __restrict__ bias,
              const float* __restrict__ gamma, const float* __restrict__ beta,
              const float* __restrict__ mean, const float* __restrict__ var,
              const float* __restrict__ resid, int Cout)
{
    extern __shared__ float sm[];
    float* s_scale = sm + OFF_SCALE;
    float* s_shift = sm + OFF_SHIFT;
    float* As = sm + OFF_A;
    float* Bs = sm + OFF_B;
    float* Cs = sm + OFF_C;

    const int tid = threadIdx.x;
    const int wid = tid >> 5, lane = tid & 31;
    const int lr = lane >> 2, lc = lane & 3;
    const int nt = blockIdx.x, mt = blockIdx.y;
    const int wm = (wid & 1) * 64, wn = (wid >> 1) * 32;

    if (tid < BN) {   // per-column BN scale/shift (bias folded for EPI 2)
        const int n = nt * BN + tid;
        const float inv = rsqrtf(var[n] + EPSV);
        const float sc = inv * gamma[n];
        float sh = beta[n] - mean[n] * sc;
        if (EPI == 2) sh += bias[n] * sc;
        s_scale[tid] = sc;
        s_shift[tid] = sh;
    }

    float c[4][4][4];
    #pragma unroll
    for (int mi = 0; mi < 4; mi++)
        #pragma unroll
        for (int ni = 0; ni < 4; ni++)
            #pragma unroll
            for (int j = 0; j < 4; j++) c[mi][ni][j] = 0.f;

    const float* Ab = A  + (size_t)(mt * BM) * Kdim;
    const float* Bb = Bw + (size_t)(nt * BN) * Kdim;
    const uint32_t* As32 = (const uint32_t*)As;
    const uint32_t* Bs32 = (const uint32_t*)Bs;

    for (int kc = 0; kc < Kdim; kc += BK) {
        __syncthreads();   // prior reads of As/Bs complete before overwrite
        #pragma unroll
        for (int i = 0; i < 4; i++) {      // 128 rows x 32 K, float4 units
            const int u = tid + i * 256, r = u >> 3, q = u & 7;
            float4 va = *(const float4*)(Ab + (size_t)r * Kdim + kc + q * 4);
            uint4 ua; ua.x = f2tf(va.x); ua.y = f2tf(va.y); ua.z = f2tf(va.z); ua.w = f2tf(va.w);
            *(uint4*)(As + r * ASTR + q * 4) = ua;
            float4 vb = *(const float4*)(Bb + (size_t)r * Kdim + kc + q * 4);
            uint4 ub; ub.x = f2tf(vb.x); ub.y = f2tf(vb.y); ub.z = f2tf(vb.z); ub.w = f2tf(vb.w);
            *(uint4*)(Bs + r * ASTR + q * 4) = ub;
        }
        __syncthreads();

        #pragma unroll
        for (int kk = 0; kk < BK; kk += 8) {
            uint32_t af[4][4], bf[4][2];
            #pragma unroll
            for (int t = 0; t < 4; t++) {              // A frags: rows wm+t*16
                const int m0 = wm + t * 16;
                af[t][0] = As32[(m0 + lr)     * ASTR + kk + lc];
                af[t][1] = As32[(m0 + lr + 8) * ASTR + kk + lc];
                af[t][2] = As32[(m0 + lr)     * ASTR + kk + lc + 4];
                af[t][3] = As32[(m0 + lr + 8) * ASTR + kk + lc + 4];
            }
            #pragma unroll
            for (int t = 0; t < 4; t++) {              // B frags: cols wn+t*8
                const int n0 = wn + t * 8;
                bf[t][0] = Bs32[(n0 + lr) * ASTR + kk + lc];
                bf[t][1] = Bs32[(n0 + lr) * ASTR + kk + lc + 4];
            }
            #pragma unroll
            for (int mi = 0; mi < 4; mi++)
                #pragma unroll
                for (int ni = 0; ni < 4; ni++)
                    mma_tf32(c[mi][ni], af[mi], bf[ni]);
        }
    }

    __syncthreads();   // all As/Bs reads done; safe to alias Cs onto them
    #pragma unroll
    for (int mi = 0; mi < 4; mi++) {
        #pragma unroll
        for (int ni = 0; ni < 4; ni++) {
            const int m0 = wm + mi * 16, n0 = wn + ni * 8;
            Cs[(m0 + lr)     * CSTR + n0 + 2 * lc]     = c[mi][ni][0];
            Cs[(m0 + lr)     * CSTR + n0 + 2 * lc + 1] = c[mi][ni][1];
            Cs[(m0 + lr + 8) * CSTR + n0 + 2 * lc]     = c[mi][ni][2];
            Cs[(m0 + lr + 8) * CSTR + n0 + 2 * lc + 1] = c[mi][ni][3];
        }
    }
    __syncthreads();

    const int P0 = mt * BM, b = P0 >> 12, p0 = P0 & 4095;
    if (EPI != 3) {
        // NHWC stream-out: n contiguous across threads (coalesced)
        #pragma unroll
        for (int i = 0; i < 64; i++) {
            const int n = tid & 127;
            const int p = i * 2 + (tid >> 7);
            const float v = fmaxf(Cs[p * CSTR + n] * s_scale[n] + s_shift[n], 0.f);
            outNHWC[(size_t)(P0 + p) * PLANES + nt * BN + n] = v;
        }
    }
    if (EPI == 1 || EPI == 3) {
        // NCHW stream-out: p contiguous across threads (coalesced)
        #pragma unroll
        for (int i = 0; i < 64; i++) {
            const int n = i * 2 + (tid >> 7);
            const int p = tid & 127;
            float v = Cs[p * CSTR + n] * s_scale[n] + s_shift[n];
            const size_t o = ((size_t)b * Cout + nt * BN + n) * NPIX + p0 + p;
            if (EPI == 3) v += resid[o];
            outNCHW[o] = fmaxf(v, 0.f);
        }
    }
}

// ======================= transpose x: [b][1024][4096] -> xT [b*4096+p][1024] =======================
__global__ __launch_bounds__(256)
void transpose_k(const float* __restrict__ x, float* __restrict__ xT)
{
    __shared__ float t[32][33];
    const int b = blockIdx.z;
    const int p0 = blockIdx.x * 32, c0 = blockIdx.y * 32;
    const float* in = x + (size_t)b * CIN * NPIX;
    float* out = xT + (size_t)b * NPIX * CIN;
    const int tx = threadIdx.x & 31, ty = threadIdx.x >> 5;   // 32 x 8
    #pragma unroll
    for (int i = 0; i < 32; i += 8)
        t[ty + i][tx] = in[(size_t)(c0 + ty + i) * NPIX + p0 + tx];
    __syncthreads();
    #pragma unroll
    for (int i = 0; i < 32; i += 8)
        out[(size_t)(p0 + ty + i) * CIN + c0 + tx] = t[tx][ty + i];
}

// ======================= w2 reshuffle: [o][c][k] -> [o][k*256+c] =======================
__global__ __launch_bounds__(256)
void w2r_k(const float* __restrict__ w2, float* __restrict__ w2r)
{
    const int idx = blockIdx.x * 256 + threadIdx.x;   // 256*2304 total
    const int o = idx / 2304, rr = idx % 2304;
    const int k = rr >> 8, cc = rr & 255;
    w2r[idx] = w2[((size_t)o * 256 + cc) * 9 + k];
}

// ======================= offset predictor, channel-split (NCHW, broadcast weights) =======================
// grid = (MTOT/256, CSPLIT); block handles 256 pixels x 32 channels -> partial acc[18]
__global__ __launch_bounds__(256)
void offset_conv_split(const float* __restrict__ out1,
                       const float* __restrict__ woff,
                       float* __restrict__ partial)
{
    const int idx = blockIdx.x * 256 + threadIdx.x;   // global pixel 0..16383
    const int b = idx >> 12;
    const int p = idx & 4095;
    const int h = p >> 6, w = p & 63;
    const int cs = blockIdx.y;

    float acc[18];
    #pragma unroll
    for (int o = 0; o < 18; o++) acc[o] = 0.f;

    const float* base = out1 + ((size_t)b * PLANES + cs * 32) * NPIX;
    #pragma unroll 2
    for (int cc = 0; cc < 32; cc++) {
        const float* pl = base + (size_t)cc * NPIX;
        float v[9];
        #pragma unroll
        for (int k = 0; k < 9; k++) {
            const int yy = h + (k / 3) * 2 - 2;
            const int xx = w + (k % 3) * 2 - 2;
            v[k] = (yy >= 0 && yy < 64 && xx >= 0 && xx < 64) ? pl[yy * 64 + xx] : 0.f;
        }
        const int c = cs * 32 + cc;
        #pragma unroll
        for (int k = 0; k < 9; k++) {
            #pragma unroll
            for (int o = 0; o < 18; o++)
                acc[o] += v[k] * woff[((size_t)o * PLANES + c) * 9 + k];
        }
    }
    #pragma unroll
    for (int o = 0; o < 18; o++)
        partial[(((size_t)cs * BATCH + b) * 18 + o) * NPIX + p] = acc[o];
}

// reduce partials: off = sum_cs partial + boff
__global__ __launch_bounds__(256)
void offset_reduce_k(const float* __restrict__ partial,
                     const float* __restrict__ boff,
                     float* __restrict__ off)
{
    const int idx = blockIdx.x * 256 + threadIdx.x;   // 4*18*4096 = 294912 total
    const int o = (idx >> 12) % 18;
    float s = boff[o];
    #pragma unroll
    for (int cs = 0; cs < CSPLIT; cs++)
        s += partial[(size_t)cs * (BATCH * 18 * NPIX) + idx];
    off[idx] = s;
}

// ======================= deformable im2col, NHWC (warp per pixel-tap) =======================
__global__ __launch_bounds__(256)
void im2col_k(const float* __restrict__ out1,   // NHWC [16384][256]
              const float* __restrict__ off,
              float* __restrict__ cols)         // [P][k*256+c]
{
    const int gw = blockIdx.x * 8 + (threadIdx.x >> 5);   // 147456 total
    const int lane = threadIdx.x & 31;
    const int k = gw % 9;
    const int P = gw / 9;
    const int b = P >> 12, p = P & 4095, h = p >> 6, w = p & 63;

    const float oy = off[((size_t)b * 18 + 2 * k)     * NPIX + p];
    const float ox = off[((size_t)b * 18 + 2 * k + 1) * NPIX + p];
    const float py = (float)((k / 3) * 2 - 2 + h) + oy;
    const float px = (float)((k % 3) * 2 - 2 + w) + ox;

    const float y0f = floorf(py), x0f = floorf(px);
    const float wy = py - y0f, wx = px - x0f;
    const int y0 = (int)y0f, x0 = (int)x0f, y1 = y0 + 1, x1 = x0 + 1;
    const float vy0 = (y0 >= 0 && y0 < 64) ? 1.f : 0.f;
    const float vy1 = (y1 >= 0 && y1 < 64) ? 1.f : 0.f;
    const float vx0 = (x0 >= 0 && x0 < 64) ? 1.f : 0.f;
    const float vx1 = (x1 >= 0 && x1 < 64) ? 1.f : 0.f;
    const int cy0 = min(max(y0, 0), 63), cy1 = min(max(y1, 0), 63);
    const int cx0 = min(max(x0, 0), 63), cx1 = min(max(x1, 0), 63);
    const float w00 = (1.f - wy) * (1.f - wx) * vy0 * vx0;
    const float w01 = (1.f - wy) * wx         * vy0 * vx1;
    const float w10 = wy         * (1.f - wx) * vy1 * vx0;
    const float w11 = wy         * wx         * vy1 * vx1;

    const size_t rb = (size_t)(b << 12);
    const float* r00 = out1 + (rb + cy0 * 64 + cx0) * PLANES;
    const float* r01 = out1 + (rb + cy0 * 64 + cx1) * PLANES;
    const float* r10 = out1 + (rb + cy1 * 64 + cx0) * PLANES;
    const float* r11 = out1 + (rb + cy1 * 64 + cx1) * PLANES;
    float* dst = cols + (size_t)P * (PLANES * 9) + k * PLANES;

    const int c0 = lane * 8;
    #pragma unroll
    for (int q = 0; q < 2; q++) {
        const int cidx = c0 + q * 4;
        const float4 a  = *(const float4*)(r00 + cidx);
        const float4 bq = *(const float4*)(r01 + cidx);
        const float4 cq = *(const float4*)(r10 + cidx);
        const float4 dq = *(const float4*)(r11 + cidx);
        float4 v;
        v.x = w00 * a.x + w01 * bq.x + w10 * cq.x + w11 * dq.x;
        v.y = w00 * a.y + w01 * bq.y + w10 * cq.y + w11 * dq.y;
        v.z = w00 * a.z + w01 * bq.z + w10 * cq.z + w11 * dq.z;
        v.w = w00 * a.w + w01 * bq.w + w10 * cq.w + w11 * dq.w;
        *(float4*)(dst + cidx) = v;
    }
}

// ======================= launch =======================
extern "C" void kernel_launch(void* const* d_in, const int* in_sizes, int n_in,
                              void* d_out, int out_size)
{
    const float* x      = (const float*)d_in[0];
    const float* w1     = (const float*)d_in[1];
    const float* gamma1 = (const float*)d_in[2];
    const float* beta1  = (const float*)d_in[3];
    const float* mean1  = (const float*)d_in[4];
    const float* var1   = (const float*)d_in[5];
    const float* woff   = (const float*)d_in[6];
    const float* boff   = (const float*)d_in[7];
    const float* w2     = (const float*)d_in[8];
    const float* bconv2 = (const float*)d_in[9];
    const float* gamma2 = (const float*)d_in[10];
    const float* beta2  = (const float*)d_in[11];
    const float* mean2  = (const float*)d_in[12];
    const float* var2   = (const float*)d_in[13];
    const float* w3     = (const float*)d_in[14];
    const float* gamma3 = (const float*)d_in[15];
    const float* beta3  = (const float*)d_in[16];
    const float* mean3  = (const float*)d_in[17];
    const float* var3   = (const float*)d_in[18];
    float* out = (float*)d_out;

    float *p_xT, *p_o1h, *p_o1c, *p_off, *p_offp, *p_cols, *p_out2, *p_w2r;
    cudaGetSymbolAddress((void**)&p_xT,   g_xT);
    cudaGetSymbolAddress((void**)&p_o1h,  g_out1_nhwc);
    cudaGetSymbolAddress((void**)&p_o1c,  g_out1_nchw);
    cudaGetSymbolAddress((void**)&p_off,  g_off);
    cudaGetSymbolAddress((void**)&p_offp, g_offp);
    cudaGetSymbolAddress((void**)&p_cols, g_cols);
    cudaGetSymbolAddress((void**)&p_out2, g_out2);
    cudaGetSymbolAddress((void**)&p_w2r,  g_w2r);

    cudaFuncSetAttribute(gemm_mma<1>, cudaFuncAttributeMaxDynamicSharedMemorySize, SM_BYTES);
    cudaFuncSetAttribute(gemm_mma<2>, cudaFuncAttributeMaxDynamicSharedMemorySize, SM_BYTES);
    cudaFuncSetAttribute(gemm_mma<3>, cudaFuncAttributeMaxDynamicSharedMemorySize, SM_BYTES);

    // independent prep
    transpose_k<<<dim3(NPIX / 32, CIN / 32, BATCH), 256>>>(x, p_xT);
    w2r_k<<<2304, 256>>>(w2, p_w2r);

    // 1) conv1: [16384,1024] x [256,1024]^T -> out1 (NHWC + NCHW), BN1+ReLU
    gemm_mma<1><<<dim3(PLANES / BN, MTOT / BM), 256, SM_BYTES>>>(
        p_xT, w1, CIN, p_o1h, p_o1c, nullptr,
        gamma1, beta1, mean1, var1, nullptr, PLANES);

    // 2) offset predictor: channel-split partials + reduce
    offset_conv_split<<<dim3(MTOT / 256, CSPLIT), 256>>>(p_o1c, woff, p_offp);
    offset_reduce_k<<<(BATCH * 18 * NPIX) / 256, 256>>>(p_offp, boff, p_off);

    // 3) deformable im2col (NHWC)
    im2col_k<<<(MTOT * 9) / 8, 256>>>(p_o1h, p_off, p_cols);

    // 4) deform GEMM: [16384,2304] x [256,2304]^T + bias, BN2+ReLU -> out2 NHWC
    gemm_mma<2><<<dim3(PLANES / BN, MTOT / BM), 256, SM_BYTES>>>(
        p_cols, p_w2r, PLANES * 9, p_out2, nullptr, bconv2,
        gamma2, beta2, mean2, var2, nullptr, PLANES);

    // 5) conv3: [16384,256] x [1024,256]^T, BN3 + residual + ReLU -> out NCHW
    gemm_mma<3><<<dim3(CIN / BN, MTOT / BM), 256, SM_BYTES>>>(
        p_out2, w3, PLANES, nullptr, out, nullptr,
        gamma3, beta3, mean3, var3, x, CIN);
}

// round 14
// speedup vs baseline: 2.7313x; 1.0694x over previous
#include <cuda_runtime.h>
#include <cstdint>
#include <cstddef>

#define BATCH   4
#define CIN     1024
#define NPIX    4096
#define MTOT    (BATCH * NPIX)      // 16384 pixels total
#define PLANES  256
#define EPSV    1e-5f

// ---------------- scratch (device globals: allocation-guard safe) ----------------
__device__ float g_xT       [(size_t)MTOT * CIN];          // 64 MB  x transposed [P][C]
__device__ float g_out1_nhwc[(size_t)MTOT * PLANES];       // 16 MB  [P][256]
__device__ float g_off      [(size_t)BATCH * 18 * NPIX];   // 1.2 MB
__device__ float g_out2     [(size_t)MTOT * PLANES];       // 16 MB  [P][256]
__device__ float g_w2r      [(size_t)PLANES * PLANES * 9]; // 2.3 MB [o][k*256+c]
__device__ float g_woffp    [(size_t)32 * PLANES * 9];     // 0.3 MB [o(pad32)][k*256+c]

// ---------------- helpers ----------------
__device__ __forceinline__ uint32_t f2tf(float f) {   // round-to-nearest tf32
    uint32_t u;
    asm("cvt.rna.tf32.f32 %0, %1;" : "=r"(u) : "f"(f));
    return u;
}
__device__ __forceinline__ void mma_tf32(float* c, const uint32_t* a, const uint32_t* b) {
    asm volatile(
        "mma.sync.aligned.m16n8k8.row.col.f32.tf32.tf32.f32 "
        "{%0,%1,%2,%3}, {%4,%5,%6,%7}, {%8,%9}, {%0,%1,%2,%3};"
        : "+f"(c[0]), "+f"(c[1]), "+f"(c[2]), "+f"(c[3])
        : "r"(a[0]), "r"(a[1]), "r"(a[2]), "r"(a[3]), "r"(b[0]), "r"(b[1]));
}

#define BM 128
#define BN 128
#define BK 32
#define ASTR 36                  // padded K-stride for A/B smem tiles
#define CSTR 133                 // padded N-stride for C staging (coprime with 32)

// smem layout (float offsets); C staging ALIASES the A/B tiles (only live post-loop)
#define OFF_SCALE 0
#define OFF_SHIFT 128
#define OFF_A     256
#define OFF_B     (OFF_A + BM * ASTR)            // 256 + 4608
#define OFF_C     OFF_A
#define SM_FLOATS (OFF_A + BM * CSTR)            // 17280 floats
#define SM_BYTES  (SM_FLOATS * 4)                // 69120 bytes -> 2 CTAs/SM

// ======================= plain tf32 GEMM (conv1 / conv3) =======================
// D[P, n] = sum_k A[P, k] * B[n, k]; CTA 128x128, BK=32, 8 warps (2M x 4N).
// EPI 1: relu(BN(acc))         -> NHWC           (conv1)
// EPI 3: relu(BN(acc) + resid) -> NCHW           (conv3, Cout=1024)
template<int EPI>
__global__ __launch_bounds__(256, 2)
void gemm_mma(const float* __restrict__ A, const float* __restrict__ Bw,
              int Kdim,
              float* __restrict__ outNHWC, float* __restrict__ outNCHW,
              const float* __restrict__ gamma, const float* __restrict__ beta,
              const float* __restrict__ mean, const float* __restrict__ var,
              const float* __restrict__ resid, int Cout)
{
    extern __shared__ float sm[];
    float* s_scale = sm + OFF_SCALE;
    float* s_shift = sm + OFF_SHIFT;
    float* As = sm + OFF_A;
    float* Bs = sm + OFF_B;
    float* Cs = sm + OFF_C;

    const int tid = threadIdx.x;
    const int wid = tid >> 5, lane = tid & 31;
    const int lr = lane >> 2, lc = lane & 3;
    const int nt = blockIdx.x, mt = blockIdx.y;
    const int wm = (wid & 1) * 64, wn = (wid >> 1) * 32;

    if (tid < BN) {
        const int n = nt * BN + tid;
        const float inv = rsqrtf(var[n] + EPSV);
        const float sc = inv * gamma[n];
        s_scale[tid] = sc;
        s_shift[tid] = beta[n] - mean[n] * sc;
    }

    float c[4][4][4];
    #pragma unroll
    for (int mi = 0; mi < 4; mi++)
        #pragma unroll
        for (int ni = 0; ni < 4; ni++)
            #pragma unroll
            for (int j = 0; j < 4; j++) c[mi][ni][j] = 0.f;

    const float* Ab = A  + (size_t)(mt * BM) * Kdim;
    const float* Bb = Bw + (size_t)(nt * BN) * Kdim;
    const uint32_t* As32 = (const uint32_t*)As;
    const uint32_t* Bs32 = (const uint32_t*)Bs;

    for (int kc = 0; kc < Kdim; kc += BK) {
        __syncthreads();
        #pragma unroll
        for (int i = 0; i < 4; i++) {
            const int u = tid + i * 256, r = u >> 3, q = u & 7;
            float4 va = *(const float4*)(Ab + (size_t)r * Kdim + kc + q * 4);
            uint4 ua; ua.x = f2tf(va.x); ua.y = f2tf(va.y); ua.z = f2tf(va.z); ua.w = f2tf(va.w);
            *(uint4*)(As + r * ASTR + q * 4) = ua;
            float4 vb = *(const float4*)(Bb + (size_t)r * Kdim + kc + q * 4);
            uint4 ub; ub.x = f2tf(vb.x); ub.y = f2tf(vb.y); ub.z = f2tf(vb.z); ub.w = f2tf(vb.w);
            *(uint4*)(Bs + r * ASTR + q * 4) = ub;
        }
        __syncthreads();

        #pragma unroll
        for (int kk = 0; kk < BK; kk += 8) {
            uint32_t af[4][4], bf[4][2];
            #pragma unroll
            for (int t = 0; t < 4; t++) {
                const int m0 = wm + t * 16;
                af[t][0] = As32[(m0 + lr)     * ASTR + kk + lc];
                af[t][1] = As32[(m0 + lr + 8) * ASTR + kk + lc];
                af[t][2] = As32[(m0 + lr)     * ASTR + kk + lc + 4];
                af[t][3] = As32[(m0 + lr + 8) * ASTR + kk + lc + 4];
            }
            #pragma unroll
            for (int t = 0; t < 4; t++) {
                const int n0 = wn + t * 8;
                bf[t][0] = Bs32[(n0 + lr) * ASTR + kk + lc];
                bf[t][1] = Bs32[(n0 + lr) * ASTR + kk + lc + 4];
            }
            #pragma unroll
            for (int mi = 0; mi < 4; mi++)
                #pragma unroll
                for (int ni = 0; ni < 4; ni++)
                    mma_tf32(c[mi][ni], af[mi], bf[ni]);
        }
    }

    __syncthreads();
    #pragma unroll
    for (int mi = 0; mi < 4; mi++) {
        #pragma unroll
        for (int ni = 0; ni < 4; ni++) {
            const int m0 = wm + mi * 16, n0 = wn + ni * 8;
            Cs[(m0 + lr)     * CSTR + n0 + 2 * lc]     = c[mi][ni][0];
            Cs[(m0 + lr)     * CSTR + n0 + 2 * lc + 1] = c[mi][ni][1];
            Cs[(m0 + lr + 8) * CSTR + n0 + 2 * lc]     = c[mi][ni][2];
            Cs[(m0 + lr + 8) * CSTR + n0 + 2 * lc + 1] = c[mi][ni][3];
        }
    }
    __syncthreads();

    const int P0 = mt * BM, b = P0 >> 12, p0 = P0 & 4095;
    if (EPI != 3) {
        #pragma unroll
        for (int i = 0; i < 64; i++) {
            const int n = tid & 127;
            const int p = i * 2 + (tid >> 7);
            const float v = fmaxf(Cs[p * CSTR + n] * s_scale[n] + s_shift[n], 0.f);
            outNHWC[(size_t)(P0 + p) * PLANES + nt * BN + n] = v;
        }
    } else {
        #pragma unroll
        for (int i = 0; i < 64; i++) {
            const int n = i * 2 + (tid >> 7);
            const int p = tid & 127;
            float v = Cs[p * CSTR + n] * s_scale[n] + s_shift[n];
            const size_t o = ((size_t)b * Cout + nt * BN + n) * NPIX + p0 + p;
            v += resid[o];
            outNCHW[o] = fmaxf(v, 0.f);
        }
    }
}

// ======================= deform GEMM: inline bilinear im2col A loader =======================
// D[P, n] = sum_{k,c} bilinear(out1, P, k)[c] * w2r[n][k*256+c]; EPI2 epilogue.
__global__ __launch_bounds__(256, 2)
void gemm_deform(const float* __restrict__ out1,   // NHWC [16384][256]
                 const float* __restrict__ off,    // [b][18][4096]
                 const float* __restrict__ Bw,     // w2r [256][2304]
                 float* __restrict__ outNHWC,
                 const float* __restrict__ bias,
                 const float* __restrict__ gamma, const float* __restrict__ beta,
                 const float* __restrict__ mean, const float* __restrict__ var)
{
    extern __shared__ float sm[];
    float* s_scale = sm + OFF_SCALE;
    float* s_shift = sm + OFF_SHIFT;
    float* As = sm + OFF_A;
    float* Bs = sm + OFF_B;
    float* Cs = sm + OFF_C;

    const int tid = threadIdx.x;
    const int wid = tid >> 5, lane = tid & 31;
    const int lr = lane >> 2, lc = lane & 3;
    const int nt = blockIdx.x, mt = blockIdx.y;
    const int wm = (wid & 1) * 64, wn = (wid >> 1) * 32;
    const int Kdim = PLANES * 9;

    if (tid < BN) {
        const int n = nt * BN + tid;
        const float inv = rsqrtf(var[n] + EPSV);
        const float sc = inv * gamma[n];
        s_scale[tid] = sc;
        s_shift[tid] = beta[n] - mean[n] * sc + bias[n] * sc;
    }

    float c[4][4][4];
    #pragma unroll
    for (int mi = 0; mi < 4; mi++)
        #pragma unroll
        for (int ni = 0; ni < 4; ni++)
            #pragma unroll
            for (int j = 0; j < 4; j++) c[mi][ni][j] = 0.f;

    const int P0 = mt * BM, b = P0 >> 12;
    const size_t rb = (size_t)(b << 12);
    const float* offb = off + (size_t)b * 18 * NPIX;
    const float* Bb = Bw + (size_t)(nt * BN) * Kdim;
    const uint32_t* As32 = (const uint32_t*)As;
    const uint32_t* Bs32 = (const uint32_t*)Bs;

    for (int kc = 0; kc < Kdim; kc += BK) {
        const int k  = kc >> 8;           // tap constant over chunk (256 % 32 == 0)
        const int c0 = kc & 255;
        const int ky = (k / 3) * 2 - 2, kx = (k % 3) * 2 - 2;
        __syncthreads();
        #pragma unroll
        for (int i = 0; i < 4; i++) {
            const int u = tid + i * 256, r = u >> 3, q = u & 7;
            // ---- bilinear gather (port of validated im2col) ----
            const int p = (P0 + r) & 4095, h = p >> 6, w = p & 63;
            const float oy = offb[(2 * k)     * NPIX + p];
            const float ox = offb[(2 * k + 1) * NPIX + p];
            const float py = (float)(ky + h) + oy;
            const float px = (float)(kx + w) + ox;
            const float y0f = floorf(py), x0f = floorf(px);
            const float wy = py - y0f, wx = px - x0f;
            const int y0 = (int)y0f, x0 = (int)x0f, y1 = y0 + 1, x1 = x0 + 1;
            const float vy0 = (y0 >= 0 && y0 < 64) ? 1.f : 0.f;
            const float vy1 = (y1 >= 0 && y1 < 64) ? 1.f : 0.f;
            const float vx0 = (x0 >= 0 && x0 < 64) ? 1.f : 0.f;
            const float vx1 = (x1 >= 0 && x1 < 64) ? 1.f : 0.f;
            const int cy0 = min(max(y0, 0), 63), cy1 = min(max(y1, 0), 63);
            const int cx0 = min(max(x0, 0), 63), cx1 = min(max(x1, 0), 63);
            const float w00 = (1.f - wy) * (1.f - wx) * vy0 * vx0;
            const float w01 = (1.f - wy) * wx         * vy0 * vx1;
            const float w10 = wy         * (1.f - wx) * vy1 * vx0;
            const float w11 = wy         * wx         * vy1 * vx1;
            const int cc = c0 + q * 4;
            const float4 a0 = *(const float4*)(out1 + (rb + cy0 * 64 + cx0) * PLANES + cc);
            const float4 a1 = *(const float4*)(out1 + (rb + cy0 * 64 + cx1) * PLANES + cc);
            const float4 a2 = *(const float4*)(out1 + (rb + cy1 * 64 + cx0) * PLANES + cc);
            const float4 a3 = *(const float4*)(out1 + (rb + cy1 * 64 + cx1) * PLANES + cc);
            uint4 ua;
            ua.x = f2tf(w00 * a0.x + w01 * a1.x + w10 * a2.x + w11 * a3.x);
            ua.y = f2tf(w00 * a0.y + w01 * a1.y + w10 * a2.y + w11 * a3.y);
            ua.z = f2tf(w00 * a0.z + w01 * a1.z + w10 * a2.z + w11 * a3.z);
            ua.w = f2tf(w00 * a0.w + w01 * a1.w + w10 * a2.w + w11 * a3.w);
            *(uint4*)(As + r * ASTR + q * 4) = ua;
            // ---- B tile (linear) ----
            float4 vb = *(const float4*)(Bb + (size_t)r * Kdim + kc + q * 4);
            uint4 ub; ub.x = f2tf(vb.x); ub.y = f2tf(vb.y); ub.z = f2tf(vb.z); ub.w = f2tf(vb.w);
            *(uint4*)(Bs + r * ASTR + q * 4) = ub;
        }
        __syncthreads();

        #pragma unroll
        for (int kk = 0; kk < BK; kk += 8) {
            uint32_t af[4][4], bf[4][2];
            #pragma unroll
            for (int t = 0; t < 4; t++) {
                const int m0 = wm + t * 16;
                af[t][0] = As32[(m0 + lr)     * ASTR + kk + lc];
                af[t][1] = As32[(m0 + lr + 8) * ASTR + kk + lc];
                af[t][2] = As32[(m0 + lr)     * ASTR + kk + lc + 4];
                af[t][3] = As32[(m0 + lr + 8) * ASTR + kk + lc + 4];
            }
            #pragma unroll
            for (int t = 0; t < 4; t++) {
                const int n0 = wn + t * 8;
                bf[t][0] = Bs32[(n0 + lr) * ASTR + kk + lc];
                bf[t][1] = Bs32[(n0 + lr) * ASTR + kk + lc + 4];
            }
            #pragma unroll
            for (int mi = 0; mi < 4; mi++)
                #pragma unroll
                for (int ni = 0; ni < 4; ni++)
                    mma_tf32(c[mi][ni], af[mi], bf[ni]);
        }
    }

    __syncthreads();
    #pragma unroll
    for (int mi = 0; mi < 4; mi++) {
        #pragma unroll
        for (int ni = 0; ni < 4; ni++) {
            const int m0 = wm + mi * 16, n0 = wn + ni * 8;
            Cs[(m0 + lr)     * CSTR + n0 + 2 * lc]     = c[mi][ni][0];
            Cs[(m0 + lr)     * CSTR + n0 + 2 * lc + 1] = c[mi][ni][1];
            Cs[(m0 + lr + 8) * CSTR + n0 + 2 * lc]     = c[mi][ni][2];
            Cs[(m0 + lr + 8) * CSTR + n0 + 2 * lc + 1] = c[mi][ni][3];
        }
    }
    __syncthreads();

    #pragma unroll
    for (int i = 0; i < 64; i++) {
        const int n = tid & 127;
        const int p = i * 2 + (tid >> 7);
        const float v = fmaxf(Cs[p * CSTR + n] * s_scale[n] + s_shift[n], 0.f);
        outNHWC[(size_t)(P0 + p) * PLANES + nt * BN + n] = v;
    }
}

// ======================= offset GEMM: shifted-window A loader, N=32 (18 used) =======================
// off[b][o][p] = sum_{k,c} out1_shift_k[P][c] * woffp[o][k*256+c] + boff[o]
__global__ __launch_bounds__(256)
void gemm_off(const float* __restrict__ out1,     // NHWC
              const float* __restrict__ Bw,       // woffp [32][2304]
              const float* __restrict__ boff,
              float* __restrict__ off)
{
    __shared__ float As[BM * ASTR];                // 4608 floats
    __shared__ float Bs[32 * ASTR];                // 1152 floats
    float* Cs = As;                                // alias: 128*33 = 4224 < 4608

    const int tid = threadIdx.x;
    const int wid = tid >> 5, lane = tid & 31;
    const int lr = lane >> 2, lc = lane & 3;
    const int mt = blockIdx.x;
    const int wm = (wid & 1) * 64, wn = (wid >> 1) * 8;
    const int Kdim = PLANES * 9;

    float c[4][4];
    #pragma unroll
    for (int mi = 0; mi < 4; mi++)
        #pragma unroll
        for (int j = 0; j < 4; j++) c[mi][j] = 0.f;

    const int P0 = mt * BM, b = P0 >> 12;
    const size_t rb = (size_t)(b << 12);
    const uint32_t* As32 = (const uint32_t*)As;
    const uint32_t* Bs32 = (const uint32_t*)Bs;

    for (int kc = 0; kc < Kdim; kc += BK) {
        const int k  = kc >> 8;
        const int c0 = kc & 255;
        const int ky = (k / 3) * 2 - 2, kx = (k % 3) * 2 - 2;
        __syncthreads();
        #pragma unroll
        for (int i = 0; i < 4; i++) {              // A: 128 rows x 32 cols, shifted gather
            const int u = tid + i * 256, r = u >> 3, q = u & 7;
            const int p = (P0 + r) & 4095, h = p >> 6, w = p & 63;
            const int yy = h + ky, xx = w + kx;
            uint4 ua;
            if (yy >= 0 && yy < 64 && xx >= 0 && xx < 64) {
                const float4 v = *(const float4*)(out1 + (rb + yy * 64 + xx) * PLANES + c0 + q * 4);
                ua.x = f2tf(v.x); ua.y = f2tf(v.y); ua.z = f2tf(v.z); ua.w = f2tf(v.w);
            } else {
                ua.x = ua.y = ua.z = ua.w = 0u;
            }
            *(uint4*)(As + r * ASTR + q * 4) = ua;
        }
        {                                          // B: 32 rows x 32 cols, one float4/thread
            const int r = tid >> 3, q = tid & 7;
            float4 vb = *(const float4*)(Bw + (size_t)r * Kdim + kc + q * 4);
            uint4 ub; ub.x = f2tf(vb.x); ub.y = f2tf(vb.y); ub.z = f2tf(vb.z); ub.w = f2tf(vb.w);
            *(uint4*)(Bs + r * ASTR + q * 4) = ub;
        }
        __syncthreads();

        #pragma unroll
        for (int kk = 0; kk < BK; kk += 8) {
            uint32_t af[4][4], bf[2];
            #pragma unroll
            for (int t = 0; t < 4; t++) {
                const int m0 = wm + t * 16;
                af[t][0] = As32[(m0 + lr)     * ASTR + kk + lc];
                af[t][1] = As32[(m0 + lr + 8) * ASTR + kk + lc];
                af[t][2] = As32[(m0 + lr)     * ASTR + kk + lc + 4];
                af[t][3] = As32[(m0 + lr + 8) * ASTR + kk + lc + 4];
            }
            bf[0] = Bs32[(wn + lr) * ASTR + kk + lc];
            bf[1] = Bs32[(wn + lr) * ASTR + kk + lc + 4];
            #pragma unroll
            for (int mi = 0; mi < 4; mi++)
                mma_tf32(c[mi], af[mi], bf);
        }
    }

    __syncthreads();
    #pragma unroll
    for (int mi = 0; mi < 4; mi++) {
        const int m0 = wm + mi * 16;
        Cs[(m0 + lr)     * 33 + wn + 2 * lc]     = c[mi][0];
        Cs[(m0 + lr)     * 33 + wn + 2 * lc + 1] = c[mi][1];
        Cs[(m0 + lr + 8) * 33 + wn + 2 * lc]     = c[mi][2];
        Cs[(m0 + lr + 8) * 33 + wn + 2 * lc + 1] = c[mi][3];
    }
    __syncthreads();

    const int p0 = P0 & 4095;
    #pragma unroll
    for (int i = 0; i < 9; i++) {                 // 18 outputs x 128 pixels
        const int o = i * 2 + (tid >> 7);
        const int p = tid & 127;
        off[((size_t)b * 18 + o) * NPIX + p0 + p] = Cs[p * 33 + o] + boff[o];
    }
}

// ======================= transpose x: [b][1024][4096] -> xT [b*4096+p][1024] =======================
__global__ __launch_bounds__(256)
void transpose_k(const float* __restrict__ x, float* __restrict__ xT)
{
    __shared__ float t[32][33];
    const int b = blockIdx.z;
    const int p0 = blockIdx.x * 32, c0 = blockIdx.y * 32;
    const float* in = x + (size_t)b * CIN * NPIX;
    float* out = xT + (size_t)b * NPIX * CIN;
    const int tx = threadIdx.x & 31, ty = threadIdx.x >> 5;
    #pragma unroll
    for (int i = 0; i < 32; i += 8)
        t[ty + i][tx] = in[(size_t)(c0 + ty + i) * NPIX + p0 + tx];
    __syncthreads();
    #pragma unroll
    for (int i = 0; i < 32; i += 8)
        out[(size_t)(p0 + ty + i) * CIN + c0 + tx] = t[tx][ty + i];
}

// ======================= weight reshuffles =======================
__global__ __launch_bounds__(256)
void w2r_k(const float* __restrict__ w2, float* __restrict__ w2r)
{
    const int idx = blockIdx.x * 256 + threadIdx.x;   // 256*2304
    const int o = idx / 2304, rr = idx % 2304;
    const int k = rr >> 8, cc = rr & 255;
    w2r[idx] = w2[((size_t)o * 256 + cc) * 9 + k];
}
__global__ __launch_bounds__(256)
void woffr_k(const float* __restrict__ woff, float* __restrict__ woffp)
{
    const int idx = blockIdx.x * 256 + threadIdx.x;   // 32*2304 = 73728
    const int o = idx / 2304, rr = idx % 2304;
    const int k = rr >> 8, cc = rr & 255;
    woffp[idx] = (o < 18) ? woff[((size_t)o * 256 + cc) * 9 + k] : 0.f;
}

// ======================= launch =======================
extern "C" void kernel_launch(void* const* d_in, const int* in_sizes, int n_in,
                              void* d_out, int out_size)
{
    const float* x      = (const float*)d_in[0];
    const float* w1     = (const float*)d_in[1];
    const float* gamma1 = (const float*)d_in[2];
    const float* beta1  = (const float*)d_in[3];
    const float* mean1  = (const float*)d_in[4];
    const float* var1   = (const float*)d_in[5];
    const float* woff   = (const float*)d_in[6];
    const float* boff   = (const float*)d_in[7];
    const float* w2     = (const float*)d_in[8];
    const float* bconv2 = (const float*)d_in[9];
    const float* gamma2 = (const float*)d_in[10];
    const float* beta2  = (const float*)d_in[11];
    const float* mean2  = (const float*)d_in[12];
    const float* var2   = (const float*)d_in[13];
    const float* w3     = (const float*)d_in[14];
    const float* gamma3 = (const float*)d_in[15];
    const float* beta3  = (const float*)d_in[16];
    const float* mean3  = (const float*)d_in[17];
    const float* var3   = (const float*)d_in[18];
    float* out = (float*)d_out;

    float *p_xT, *p_o1h, *p_off, *p_out2, *p_w2r, *p_woffp;
    cudaGetSymbolAddress((void**)&p_xT,    g_xT);
    cudaGetSymbolAddress((void**)&p_o1h,   g_out1_nhwc);
    cudaGetSymbolAddress((void**)&p_off,   g_off);
    cudaGetSymbolAddress((void**)&p_out2,  g_out2);
    cudaGetSymbolAddress((void**)&p_w2r,   g_w2r);
    cudaGetSymbolAddress((void**)&p_woffp, g_woffp);

    cudaFuncSetAttribute(gemm_mma<1>, cudaFuncAttributeMaxDynamicSharedMemorySize, SM_BYTES);
    cudaFuncSetAttribute(gemm_mma<3>, cudaFuncAttributeMaxDynamicSharedMemorySize, SM_BYTES);
    cudaFuncSetAttribute(gemm_deform, cudaFuncAttributeMaxDynamicSharedMemorySize, SM_BYTES);

    // independent prep
    transpose_k<<<dim3(NPIX / 32, CIN / 32, BATCH), 256>>>(x, p_xT);
    w2r_k<<<2304, 256>>>(w2, p_w2r);
    woffr_k<<<288, 256>>>(woff, p_woffp);

    // 1) conv1: [16384,1024] x [256,1024]^T -> out1 NHWC, BN1+ReLU
    gemm_mma<1><<<dim3(PLANES / BN, MTOT / BM), 256, SM_BYTES>>>(
        p_xT, w1, CIN, p_o1h, nullptr,
        gamma1, beta1, mean1, var1, nullptr, PLANES);

    // 2) offset predictor as GEMM (shifted-window gather A)
    gemm_off<<<MTOT / BM, 256>>>(p_o1h, p_woffp, boff, p_off);

    // 3) deform GEMM with inline bilinear im2col + bias + BN2 + ReLU -> out2 NHWC
    gemm_deform<<<dim3(PLANES / BN, MTOT / BM), 256, SM_BYTES>>>(
        p_o1h, p_off, p_w2r, p_out2, bconv2,
        gamma2, beta2, mean2, var2);

    // 4) conv3: [16384,256] x [1024,256]^T, BN3 + residual + ReLU -> out NCHW
    gemm_mma<3><<<dim3(CIN / BN, MTOT / BM), 256, SM_BYTES>>>(
        p_out2, w3, PLANES, nullptr, out,
        gamma3, beta3, mean3, var3, x, CIN);
}

// round 15
// speedup vs baseline: 2.8335x; 1.0374x over previous
#include <cuda_runtime.h>
#include <cstdint>
#include <cstddef>

#define BATCH   4
#define CIN     1024
#define NPIX    4096
#define MTOT    (BATCH * NPIX)      // 16384 pixels total
#define PLANES  256
#define EPSV    1e-5f

// ---------------- scratch (device globals: allocation-guard safe) ----------------
__device__ float g_xT       [(size_t)MTOT * CIN];          // 64 MB  x transposed [P][C]
__device__ float g_out1_nhwc[(size_t)MTOT * PLANES];       // 16 MB  [P][256]
__device__ float g_off      [(size_t)BATCH * 18 * NPIX];   // 1.2 MB
__device__ float g_out2     [(size_t)MTOT * PLANES];       // 16 MB  [P][256]
__device__ float g_w2r      [(size_t)PLANES * PLANES * 9]; // 2.3 MB [o][k*256+c]
__device__ float g_woffp    [(size_t)32 * PLANES * 9];     // 0.3 MB [o(pad32)][k*256+c]

// ---------------- helpers ----------------
__device__ __forceinline__ uint32_t f2tf(float f) {   // round-to-nearest tf32
    uint32_t u;
    asm("cvt.rna.tf32.f32 %0, %1;" : "=r"(u) : "f"(f));
    return u;
}
__device__ __forceinline__ void mma_tf32(float* c, const uint32_t* a, const uint32_t* b) {
    asm volatile(
        "mma.sync.aligned.m16n8k8.row.col.f32.tf32.tf32.f32 "
        "{%0,%1,%2,%3}, {%4,%5,%6,%7}, {%8,%9}, {%0,%1,%2,%3};"
        : "+f"(c[0]), "+f"(c[1]), "+f"(c[2]), "+f"(c[3])
        : "r"(a[0]), "r"(a[1]), "r"(a[2]), "r"(a[3]), "r"(b[0]), "r"(b[1]));
}
__device__ __forceinline__ uint32_t smem_u32(const void* p) {
    uint32_t a;
    asm("{ .reg .u64 t; cvta.to.shared.u64 t, %1; cvt.u32.u64 %0, t; }" : "=r"(a) : "l"(p));
    return a;
}
__device__ __forceinline__ void cp_async16(uint32_t dst, const void* src) {
    asm volatile("cp.async.cg.shared.global [%0], [%1], 16;" :: "r"(dst), "l"(src));
}
#define CP_COMMIT()  asm volatile("cp.async.commit_group;" ::: "memory")
#define CP_WAIT(n)   asm volatile("cp.async.wait_group %0;" :: "n"(n) : "memory")

#define BM 128
#define BN 128
#define BK 32
#define ASTR 36                  // padded K-stride for A/B smem tiles
#define CSTR 133                 // padded N-stride for C staging (coprime with 32)

// ======== plain GEMM smem layout (double-buffered, fp32 staging) ========
#define P_SCALE   0
#define P_SHIFT   128
#define P_TILES   256
#define P_STAGE   9216                       // A(4608) + B(4608) floats per stage
#define P_BOFF    4608                       // B offset within a stage
#define P_FLOATS  (P_TILES + 2 * P_STAGE)    // 18688 floats
#define P_BYTES   (P_FLOATS * 4)             // 74752 B -> 2 CTAs w/ max carveout

// ======== deform GEMM smem layout (single-buffered, tf32 staging) ========
#define OFF_SCALE 0
#define OFF_SHIFT 128
#define OFF_A     256
#define OFF_B     (OFF_A + BM * ASTR)
#define OFF_C     OFF_A
#define SM_FLOATS (OFF_A + BM * CSTR)
#define SM_BYTES  (SM_FLOATS * 4)            // 69120 B

// ======================= plain tf32 GEMM, cp.async double-buffered =======================
// D[P, n] = sum_k A[P, k] * B[n, k]; CTA 128x128, BK=32, 8 warps (2M x 4N).
// EPI 1: relu(BN(acc))         -> NHWC   (conv1)
// EPI 3: relu(BN(acc) + resid) -> NCHW   (conv3, Cout=1024)
template<int EPI>
__global__ __launch_bounds__(256, 2)
void gemm_mma(const float* __restrict__ A, const float* __restrict__ Bw,
              int Kdim,
              float* __restrict__ outNHWC, float* __restrict__ outNCHW,
              const float* __restrict__ gamma, const float* __restrict__ beta,
              const float* __restrict__ mean, const float* __restrict__ var,
              const float* __restrict__ resid, int Cout)
{
    extern __shared__ float sm[];
    float* s_scale = sm + P_SCALE;
    float* s_shift = sm + P_SHIFT;
    float* Cs = sm + P_TILES;                 // epilogue staging aliases the tiles

    const int tid = threadIdx.x;
    const int wid = tid >> 5, lane = tid & 31;
    const int lr = lane >> 2, lc = lane & 3;
    const int nt = blockIdx.x, mt = blockIdx.y;
    const int wm = (wid & 1) * 64, wn = (wid >> 1) * 32;

    if (tid < BN) {
        const int n = nt * BN + tid;
        const float inv = rsqrtf(var[n] + EPSV);
        const float sc = inv * gamma[n];
        s_scale[tid] = sc;
        s_shift[tid] = beta[n] - mean[n] * sc;
    }

    float c[4][4][4];
    #pragma unroll
    for (int mi = 0; mi < 4; mi++)
        #pragma unroll
        for (int ni = 0; ni < 4; ni++)
            #pragma unroll
            for (int j = 0; j < 4; j++) c[mi][ni][j] = 0.f;

    const float* Ab = A  + (size_t)(mt * BM) * Kdim;
    const float* Bb = Bw + (size_t)(nt * BN) * Kdim;
    const int r_ld = tid >> 3, q_ld = tid & 7;          // per-thread loader coords
    const uint32_t smbase = smem_u32(sm + P_TILES);
    const int NC = Kdim / BK;

    // loader: one 16B A line + one 16B B line per thread per i (4 i's = full tiles)
    auto load_stage = [&](int s, int kc) {
        const uint32_t stage = smbase + (uint32_t)(s * P_STAGE) * 4u;
        #pragma unroll
        for (int i = 0; i < 4; i++) {
            const int r = r_ld + i * 32;
            cp_async16(stage + (uint32_t)(r * ASTR + q_ld * 4) * 4u,
                       Ab + (size_t)r * Kdim + kc + q_ld * 4);
            cp_async16(stage + (uint32_t)(P_BOFF + r * ASTR + q_ld * 4) * 4u,
                       Bb + (size_t)r * Kdim + kc + q_ld * 4);
        }
    };

    load_stage(0, 0);
    CP_COMMIT();

    for (int it = 0; it < NC; ++it) {
        const int s = it & 1;
        if (it + 1 < NC) {
            load_stage(s ^ 1, (it + 1) * BK);
            CP_COMMIT();
            CP_WAIT(1);
        } else {
            CP_WAIT(0);
        }
        __syncthreads();

        const float* As = sm + P_TILES + s * P_STAGE;
        const float* Bs = As + P_BOFF;
        #pragma unroll
        for (int kk = 0; kk < BK; kk += 8) {
            uint32_t af[4][4], bf[4][2];
            #pragma unroll
            for (int t = 0; t < 4; t++) {
                const int m0 = wm + t * 16;
                af[t][0] = f2tf(As[(m0 + lr)     * ASTR + kk + lc]);
                af[t][1] = f2tf(As[(m0 + lr + 8) * ASTR + kk + lc]);
                af[t][2] = f2tf(As[(m0 + lr)     * ASTR + kk + lc + 4]);
                af[t][3] = f2tf(As[(m0 + lr + 8) * ASTR + kk + lc + 4]);
            }
            #pragma unroll
            for (int t = 0; t < 4; t++) {
                const int n0 = wn + t * 8;
                bf[t][0] = f2tf(Bs[(n0 + lr) * ASTR + kk + lc]);
                bf[t][1] = f2tf(Bs[(n0 + lr) * ASTR + kk + lc + 4]);
            }
            #pragma unroll
            for (int mi = 0; mi < 4; mi++)
                #pragma unroll
                for (int ni = 0; ni < 4; ni++)
                    mma_tf32(c[mi][ni], af[mi], bf[ni]);
        }
        __syncthreads();
    }

    #pragma unroll
    for (int mi = 0; mi < 4; mi++) {
        #pragma unroll
        for (int ni = 0; ni < 4; ni++) {
            const int m0 = wm + mi * 16, n0 = wn + ni * 8;
            Cs[(m0 + lr)     * CSTR + n0 + 2 * lc]     = c[mi][ni][0];
            Cs[(m0 + lr)     * CSTR + n0 + 2 * lc + 1] = c[mi][ni][1];
            Cs[(m0 + lr + 8) * CSTR + n0 + 2 * lc]     = c[mi][ni][2];
            Cs[(m0 + lr + 8) * CSTR + n0 + 2 * lc + 1] = c[mi][ni][3];
        }
    }
    __syncthreads();

    const int P0 = mt * BM, b = P0 >> 12, p0 = P0 & 4095;
    if (EPI != 3) {
        #pragma unroll
        for (int i = 0; i < 64; i++) {
            const int n = tid & 127;
            const int p = i * 2 + (tid >> 7);
            const float v = fmaxf(Cs[p * CSTR + n] * s_scale[n] + s_shift[n], 0.f);
            outNHWC[(size_t)(P0 + p) * PLANES + nt * BN + n] = v;
        }
    } else {
        #pragma unroll
        for (int i = 0; i < 64; i++) {
            const int n = i * 2 + (tid >> 7);
            const int p = tid & 127;
            float v = Cs[p * CSTR + n] * s_scale[n] + s_shift[n];
            const size_t o = ((size_t)b * Cout + nt * BN + n) * NPIX + p0 + p;
            v += resid[o];
            outNCHW[o] = fmaxf(v, 0.f);
        }
    }
}

// ======================= deform GEMM: inline bilinear im2col A loader (validated R13) =======================
__global__ __launch_bounds__(256, 2)
void gemm_deform(const float* __restrict__ out1,   // NHWC [16384][256]
                 const float* __restrict__ off,    // [b][18][4096]
                 const float* __restrict__ Bw,     // w2r [256][2304]
                 float* __restrict__ outNHWC,
                 const float* __restrict__ bias,
                 const float* __restrict__ gamma, const float* __restrict__ beta,
                 const float* __restrict__ mean, const float* __restrict__ var)
{
    extern __shared__ float sm[];
    float* s_scale = sm + OFF_SCALE;
    float* s_shift = sm + OFF_SHIFT;
    float* As = sm + OFF_A;
    float* Bs = sm + OFF_B;
    float* Cs = sm + OFF_C;

    const int tid = threadIdx.x;
    const int wid = tid >> 5, lane = tid & 31;
    const int lr = lane >> 2, lc = lane & 3;
    const int nt = blockIdx.x, mt = blockIdx.y;
    const int wm = (wid & 1) * 64, wn = (wid >> 1) * 32;
    const int Kdim = PLANES * 9;

    if (tid < BN) {
        const int n = nt * BN + tid;
        const float inv = rsqrtf(var[n] + EPSV);
        const float sc = inv * gamma[n];
        s_scale[tid] = sc;
        s_shift[tid] = beta[n] - mean[n] * sc + bias[n] * sc;
    }

    float c[4][4][4];
    #pragma unroll
    for (int mi = 0; mi < 4; mi++)
        #pragma unroll
        for (int ni = 0; ni < 4; ni++)
            #pragma unroll
            for (int j = 0; j < 4; j++) c[mi][ni][j] = 0.f;

    const int P0 = mt * BM, b = P0 >> 12;
    const size_t rb = (size_t)(b << 12);
    const float* offb = off + (size_t)b * 18 * NPIX;
    const float* Bb = Bw + (size_t)(nt * BN) * Kdim;
    const uint32_t* As32 = (const uint32_t*)As;
    const uint32_t* Bs32 = (const uint32_t*)Bs;

    for (int kc = 0; kc < Kdim; kc += BK) {
        const int k  = kc >> 8;           // tap constant over chunk (256 % 32 == 0)
        const int c0 = kc & 255;
        const int ky = (k / 3) * 2 - 2, kx = (k % 3) * 2 - 2;
        __syncthreads();
        #pragma unroll
        for (int i = 0; i < 4; i++) {
            const int u = tid + i * 256, r = u >> 3, q = u & 7;
            const int p = (P0 + r) & 4095, h = p >> 6, w = p & 63;
            const float oy = offb[(2 * k)     * NPIX + p];
            const float ox = offb[(2 * k + 1) * NPIX + p];
            const float py = (float)(ky + h) + oy;
            const float px = (float)(kx + w) + ox;
            const float y0f = floorf(py), x0f = floorf(px);
            const float wy = py - y0f, wx = px - x0f;
            const int y0 = (int)y0f, x0 = (int)x0f, y1 = y0 + 1, x1 = x0 + 1;
            const float vy0 = (y0 >= 0 && y0 < 64) ? 1.f : 0.f;
            const float vy1 = (y1 >= 0 && y1 < 64) ? 1.f : 0.f;
            const float vx0 = (x0 >= 0 && x0 < 64) ? 1.f : 0.f;
            const float vx1 = (x1 >= 0 && x1 < 64) ? 1.f : 0.f;
            const int cy0 = min(max(y0, 0), 63), cy1 = min(max(y1, 0), 63);
            const int cx0 = min(max(x0, 0), 63), cx1 = min(max(x1, 0), 63);
            const float w00 = (1.f - wy) * (1.f - wx) * vy0 * vx0;
            const float w01 = (1.f - wy) * wx         * vy0 * vx1;
            const float w10 = wy         * (1.f - wx) * vy1 * vx0;
            const float w11 = wy         * wx         * vy1 * vx1;
            const int cc = c0 + q * 4;
            const float4 a0 = *(const float4*)(out1 + (rb + cy0 * 64 + cx0) * PLANES + cc);
            const float4 a1 = *(const float4*)(out1 + (rb + cy0 * 64 + cx1) * PLANES + cc);
            const float4 a2 = *(const float4*)(out1 + (rb + cy1 * 64 + cx0) * PLANES + cc);
            const float4 a3 = *(const float4*)(out1 + (rb + cy1 * 64 + cx1) * PLANES + cc);
            uint4 ua;
            ua.x = f2tf(w00 * a0.x + w01 * a1.x + w10 * a2.x + w11 * a3.x);
            ua.y = f2tf(w00 * a0.y + w01 * a1.y + w10 * a2.y + w11 * a3.y);
            ua.z = f2tf(w00 * a0.z + w01 * a1.z + w10 * a2.z + w11 * a3.z);
            ua.w = f2tf(w00 * a0.w + w01 * a1.w + w10 * a2.w + w11 * a3.w);
            *(uint4*)(As + r * ASTR + q * 4) = ua;
            float4 vb = *(const float4*)(Bb + (size_t)r * Kdim + kc + q * 4);
            uint4 ub; ub.x = f2tf(vb.x); ub.y = f2tf(vb.y); ub.z = f2tf(vb.z); ub.w = f2tf(vb.w);
            *(uint4*)(Bs + r * ASTR + q * 4) = ub;
        }
        __syncthreads();

        #pragma unroll
        for (int kk = 0; kk < BK; kk += 8) {
            uint32_t af[4][4], bf[4][2];
            #pragma unroll
            for (int t = 0; t < 4; t++) {
                const int m0 = wm + t * 16;
                af[t][0] = As32[(m0 + lr)     * ASTR + kk + lc];
                af[t][1] = As32[(m0 + lr + 8) * ASTR + kk + lc];
                af[t][2] = As32[(m0 + lr)     * ASTR + kk + lc + 4];
                af[t][3] = As32[(m0 + lr + 8) * ASTR + kk + lc + 4];
            }
            #pragma unroll
            for (int t = 0; t < 4; t++) {
                const int n0 = wn + t * 8;
                bf[t][0] = Bs32[(n0 + lr) * ASTR + kk + lc];
                bf[t][1] = Bs32[(n0 + lr) * ASTR + kk + lc + 4];
            }
            #pragma unroll
            for (int mi = 0; mi < 4; mi++)
                #pragma unroll
                for (int ni = 0; ni < 4; ni++)
                    mma_tf32(c[mi][ni], af[mi], bf[ni]);
        }
    }

    __syncthreads();
    #pragma unroll
    for (int mi = 0; mi < 4; mi++) {
        #pragma unroll
        for (int ni = 0; ni < 4; ni++) {
            const int m0 = wm + mi * 16, n0 = wn + ni * 8;
            Cs[(m0 + lr)     * CSTR + n0 + 2 * lc]     = c[mi][ni][0];
            Cs[(m0 + lr)     * CSTR + n0 + 2 * lc + 1] = c[mi][ni][1];
            Cs[(m0 + lr + 8) * CSTR + n0 + 2 * lc]     = c[mi][ni][2];
            Cs[(m0 + lr + 8) * CSTR + n0 + 2 * lc + 1] = c[mi][ni][3];
        }
    }
    __syncthreads();

    const int P0b = mt * BM;
    #pragma unroll
    for (int i = 0; i < 64; i++) {
        const int n = tid & 127;
        const int p = i * 2 + (tid >> 7);
        const float v = fmaxf(Cs[p * CSTR + n] * s_scale[n] + s_shift[n], 0.f);
        outNHWC[(size_t)(P0b + p) * PLANES + nt * BN + n] = v;
    }
}

// ======================= offset GEMM: shifted-window A loader, N=32 (18 used) =======================
__global__ __launch_bounds__(256)
void gemm_off(const float* __restrict__ out1,     // NHWC
              const float* __restrict__ Bw,       // woffp [32][2304]
              const float* __restrict__ boff,
              float* __restrict__ off)
{
    __shared__ float As[BM * ASTR];
    __shared__ float Bs[32 * ASTR];
    float* Cs = As;                                // alias: 128*33 = 4224 < 4608

    const int tid = threadIdx.x;
    const int wid = tid >> 5, lane = tid & 31;
    const int lr = lane >> 2, lc = lane & 3;
    const int mt = blockIdx.x;
    const int wm = (wid & 1) * 64, wn = (wid >> 1) * 8;
    const int Kdim = PLANES * 9;

    float c[4][4];
    #pragma unroll
    for (int mi = 0; mi < 4; mi++)
        #pragma unroll
        for (int j = 0; j < 4; j++) c[mi][j] = 0.f;

    const int P0 = mt * BM, b = P0 >> 12;
    const size_t rb = (size_t)(b << 12);
    const uint32_t* As32 = (const uint32_t*)As;
    const uint32_t* Bs32 = (const uint32_t*)Bs;

    for (int kc = 0; kc < Kdim; kc += BK) {
        const int k  = kc >> 8;
        const int c0 = kc & 255;
        const int ky = (k / 3) * 2 - 2, kx = (k % 3) * 2 - 2;
        __syncthreads();
        #pragma unroll
        for (int i = 0; i < 4; i++) {
            const int u = tid + i * 256, r = u >> 3, q = u & 7;
            const int p = (P0 + r) & 4095, h = p >> 6, w = p & 63;
            const int yy = h + ky, xx = w + kx;
            uint4 ua;
            if (yy >= 0 && yy < 64 && xx >= 0 && xx < 64) {
                const float4 v = *(const float4*)(out1 + (rb + yy * 64 + xx) * PLANES + c0 + q * 4);
                ua.x = f2tf(v.x); ua.y = f2tf(v.y); ua.z = f2tf(v.z); ua.w = f2tf(v.w);
            } else {
                ua.x = ua.y = ua.z = ua.w = 0u;
            }
            *(uint4*)(As + r * ASTR + q * 4) = ua;
        }
        {
            const int r = tid >> 3, q = tid & 7;
            float4 vb = *(const float4*)(Bw + (size_t)r * Kdim + kc + q * 4);
            uint4 ub; ub.x = f2tf(vb.x); ub.y = f2tf(vb.y); ub.z = f2tf(vb.z); ub.w = f2tf(vb.w);
            *(uint4*)(Bs + r * ASTR + q * 4) = ub;
        }
        __syncthreads();

        #pragma unroll
        for (int kk = 0; kk < BK; kk += 8) {
            uint32_t af[4][4], bf[2];
            #pragma unroll
            for (int t = 0; t < 4; t++) {
                const int m0 = wm + t * 16;
                af[t][0] = As32[(m0 + lr)     * ASTR + kk + lc];
                af[t][1] = As32[(m0 + lr + 8) * ASTR + kk + lc];
                af[t][2] = As32[(m0 + lr)     * ASTR + kk + lc + 4];
                af[t][3] = As32[(m0 + lr + 8) * ASTR + kk + lc + 4];
            }
            bf[0] = Bs32[(wn + lr) * ASTR + kk + lc];
            bf[1] = Bs32[(wn + lr) * ASTR + kk + lc + 4];
            #pragma unroll
            for (int mi = 0; mi < 4; mi++)
                mma_tf32(c[mi], af[mi], bf);
        }
    }

    __syncthreads();
    #pragma unroll
    for (int mi = 0; mi < 4; mi++) {
        const int m0 = wm + mi * 16;
        Cs[(m0 + lr)     * 33 + wn + 2 * lc]     = c[mi][0];
        Cs[(m0 + lr)     * 33 + wn + 2 * lc + 1] = c[mi][1];
        Cs[(m0 + lr + 8) * 33 + wn + 2 * lc]     = c[mi][2];
        Cs[(m0 + lr + 8) * 33 + wn + 2 * lc + 1] = c[mi][3];
    }
    __syncthreads();

    const int p0 = P0 & 4095;
    #pragma unroll
    for (int i = 0; i < 9; i++) {
        const int o = i * 2 + (tid >> 7);
        const int p = tid & 127;
        off[((size_t)b * 18 + o) * NPIX + p0 + p] = Cs[p * 33 + o] + boff[o];
    }
}

// ======================= transpose x: [b][1024][4096] -> xT [b*4096+p][1024] =======================
__global__ __launch_bounds__(256)
void transpose_k(const float* __restrict__ x, float* __restrict__ xT)
{
    __shared__ float t[32][33];
    const int b = blockIdx.z;
    const int p0 = blockIdx.x * 32, c0 = blockIdx.y * 32;
    const float* in = x + (size_t)b * CIN * NPIX;
    float* out = xT + (size_t)b * NPIX * CIN;
    const int tx = threadIdx.x & 31, ty = threadIdx.x >> 5;
    #pragma unroll
    for (int i = 0; i < 32; i += 8)
        t[ty + i][tx] = in[(size_t)(c0 + ty + i) * NPIX + p0 + tx];
    __syncthreads();
    #pragma unroll
    for (int i = 0; i < 32; i += 8)
        out[(size_t)(p0 + ty + i) * CIN + c0 + tx] = t[tx][ty + i];
}

// ======================= weight reshuffles =======================
__global__ __launch_bounds__(256)
void w2r_k(const float* __restrict__ w2, float* __restrict__ w2r)
{
    const int idx = blockIdx.x * 256 + threadIdx.x;
    const int o = idx / 2304, rr = idx % 2304;
    const int k = rr >> 8, cc = rr & 255;
    w2r[idx] = w2[((size_t)o * 256 + cc) * 9 + k];
}
__global__ __launch_bounds__(256)
void woffr_k(const float* __restrict__ woff, float* __restrict__ woffp)
{
    const int idx = blockIdx.x * 256 + threadIdx.x;
    const int o = idx / 2304, rr = idx % 2304;
    const int k = rr >> 8, cc = rr & 255;
    woffp[idx] = (o < 18) ? woff[((size_t)o * 256 + cc) * 9 + k] : 0.f;
}

// ======================= launch =======================
extern "C" void kernel_launch(void* const* d_in, const int* in_sizes, int n_in,
                              void* d_out, int out_size)
{
    const float* x      = (const float*)d_in[0];
    const float* w1     = (const float*)d_in[1];
    const float* gamma1 = (const float*)d_in[2];
    const float* beta1  = (const float*)d_in[3];
    const float* mean1  = (const float*)d_in[4];
    const float* var1   = (const float*)d_in[5];
    const float* woff   = (const float*)d_in[6];
    const float* boff   = (const float*)d_in[7];
    const float* w2     = (const float*)d_in[8];
    const float* bconv2 = (const float*)d_in[9];
    const float* gamma2 = (const float*)d_in[10];
    const float* beta2  = (const float*)d_in[11];
    const float* mean2  = (const float*)d_in[12];
    const float* var2   = (const float*)d_in[13];
    const float* w3     = (const float*)d_in[14];
    const float* gamma3 = (const float*)d_in[15];
    const float* beta3  = (const float*)d_in[16];
    const float* mean3  = (const float*)d_in[17];
    const float* var3   = (const float*)d_in[18];
    float* out = (float*)d_out;

    float *p_xT, *p_o1h, *p_off, *p_out2, *p_w2r, *p_woffp;
    cudaGetSymbolAddress((void**)&p_xT,    g_xT);
    cudaGetSymbolAddress((void**)&p_o1h,   g_out1_nhwc);
    cudaGetSymbolAddress((void**)&p_off,   g_off);
    cudaGetSymbolAddress((void**)&p_out2,  g_out2);
    cudaGetSymbolAddress((void**)&p_w2r,   g_w2r);
    cudaGetSymbolAddress((void**)&p_woffp, g_woffp);

    cudaFuncSetAttribute(gemm_mma<1>, cudaFuncAttributeMaxDynamicSharedMemorySize, P_BYTES);
    cudaFuncSetAttribute(gemm_mma<3>, cudaFuncAttributeMaxDynamicSharedMemorySize, P_BYTES);
    cudaFuncSetAttribute(gemm_deform, cudaFuncAttributeMaxDynamicSharedMemorySize, SM_BYTES);
    // force max smem carveout so 2 CTAs/SM can co-reside
    cudaFuncSetAttribute(gemm_mma<1>, cudaFuncAttributePreferredSharedMemoryCarveout, 100);
    cudaFuncSetAttribute(gemm_mma<3>, cudaFuncAttributePreferredSharedMemoryCarveout, 100);
    cudaFuncSetAttribute(gemm_deform, cudaFuncAttributePreferredSharedMemoryCarveout, 100);

    // independent prep
    transpose_k<<<dim3(NPIX / 32, CIN / 32, BATCH), 256>>>(x, p_xT);
    w2r_k<<<2304, 256>>>(w2, p_w2r);
    woffr_k<<<288, 256>>>(woff, p_woffp);

    // 1) conv1: [16384,1024] x [256,1024]^T -> out1 NHWC, BN1+ReLU
    gemm_mma<1><<<dim3(PLANES / BN, MTOT / BM), 256, P_BYTES>>>(
        p_xT, w1, CIN, p_o1h, nullptr,
        gamma1, beta1, mean1, var1, nullptr, PLANES);

    // 2) offset predictor as GEMM (shifted-window gather A)
    gemm_off<<<MTOT / BM, 256>>>(p_o1h, p_woffp, boff, p_off);

    // 3) deform GEMM with inline bilinear im2col + bias + BN2 + ReLU -> out2 NHWC
    gemm_deform<<<dim3(PLANES / BN, MTOT / BM), 256, SM_BYTES>>>(
        p_o1h, p_off, p_w2r, p_out2, bconv2,
        gamma2, beta2, mean2, var2);

    // 4) conv3: [16384,256] x [1024,256]^T, BN3 + residual + ReLU -> out NCHW
    gemm_mma<3><<<dim3(CIN / BN, MTOT / BM), 256, P_BYTES>>>(
        p_out2, w3, PLANES, nullptr, out,
        gamma3, beta3, mean3, var3, x, CIN);
}

// round 16
// speedup vs baseline: 2.8823x; 1.0172x over previous
#include <cuda_runtime.h>
#include <cstdint>
#include <cstddef>

#define BATCH   4
#define CIN     1024
#define NPIX    4096
#define MTOT    (BATCH * NPIX)      // 16384 pixels total
#define PLANES  256
#define EPSV    1e-5f

// ---------------- scratch (device globals: allocation-guard safe) ----------------
__device__ float g_xT       [(size_t)MTOT * CIN];          // 64 MB  x transposed [P][C]
__device__ float g_out1_nhwc[(size_t)MTOT * PLANES];       // 16 MB  [P][256]
__device__ float g_off      [(size_t)BATCH * 18 * NPIX];   // 1.2 MB
__device__ float g_out2     [(size_t)MTOT * PLANES];       // 16 MB  [P][256]
__device__ float g_w2r      [(size_t)PLANES * PLANES * 9]; // 2.3 MB [o][k*256+c]
__device__ float g_woffp    [(size_t)32 * PLANES * 9];     // 0.3 MB [o(pad32)][k*256+c]

// ---------------- helpers ----------------
__device__ __forceinline__ uint32_t f2tf(float f) {   // round-to-nearest tf32
    uint32_t u;
    asm("cvt.rna.tf32.f32 %0, %1;" : "=r"(u) : "f"(f));
    return u;
}
__device__ __forceinline__ void mma_tf32(float* c, const uint32_t* a, const uint32_t* b) {
    asm volatile(
        "mma.sync.aligned.m16n8k8.row.col.f32.tf32.tf32.f32 "
        "{%0,%1,%2,%3}, {%4,%5,%6,%7}, {%8,%9}, {%0,%1,%2,%3};"
        : "+f"(c[0]), "+f"(c[1]), "+f"(c[2]), "+f"(c[3])
        : "r"(a[0]), "r"(a[1]), "r"(a[2]), "r"(a[3]), "r"(b[0]), "r"(b[1]));
}
__device__ __forceinline__ uint32_t smem_u32(const void* p) {
    uint32_t a;
    asm("{ .reg .u64 t; cvta.to.shared.u64 t, %1; cvt.u32.u64 %0, t; }" : "=r"(a) : "l"(p));
    return a;
}
__device__ __forceinline__ void cp_async16(uint32_t dst, const void* src) {
    asm volatile("cp.async.cg.shared.global [%0], [%1], 16;" :: "r"(dst), "l"(src));
}
#define CP_COMMIT()  asm volatile("cp.async.commit_group;" ::: "memory")
#define CP_WAIT(n)   asm volatile("cp.async.wait_group %0;" :: "n"(n) : "memory")

#define BM   128
#define BN2  256                 // wide CTA tile: 128x256, 512 threads, 16 warps (2M x 8N)
#define BK   32
#define ASTR 36                  // padded K-stride for A/B smem tiles
#define CSTR 133                 // padded N-stride for C staging (coprime with 32)

// ======== plain GEMM smem (double-buffered fp32 staging, 512 thr) ========
#define P_SCALE   0
#define P_SHIFT   256
#define P_TILES   512
#define P_STAGE   13824                      // A(128*36=4608) + B(256*36=9216)
#define P_BOFF    4608
#define P_FLOATS  (P_TILES + 2 * P_STAGE)    // 28160 floats
#define P_BYTES   (P_FLOATS * 4)             // 112640 B (1 CTA/SM)
// C staging (128*133=17024 floats) aliases the tile region (27648 floats)

// ======== deform GEMM smem (single-buffered tf32 staging, 512 thr) ========
#define D_SCALE   0
#define D_SHIFT   256
#define D_A       512
#define D_B       (D_A + BM * ASTR)          // 512 + 4608
#define D_FLOATS  (D_A + BM * CSTR)          // 512 + 17024 = 17536 (covers tiles 13824 + C alias)
#define D_BYTES   (D_FLOATS * 4)             // 70144 B

// ======================= plain tf32 GEMM, cp.async double-buffered, 128x256 =======================
// EPI 1: relu(BN(acc))         -> NHWC   (conv1)
// EPI 3: relu(BN(acc) + resid) -> NCHW   (conv3, Cout=1024)
template<int EPI>
__global__ __launch_bounds__(512, 1)
void gemm_mma(const float* __restrict__ A, const float* __restrict__ Bw,
              int Kdim,
              float* __restrict__ outNHWC, float* __restrict__ outNCHW,
              const float* __restrict__ gamma, const float* __restrict__ beta,
              const float* __restrict__ mean, const float* __restrict__ var,
              const float* __restrict__ resid, int Cout)
{
    extern __shared__ float sm[];
    float* s_scale = sm + P_SCALE;
    float* s_shift = sm + P_SHIFT;
    float* Cs = sm + P_TILES;                 // aliases tiles (post-loop / between passes)

    const int tid = threadIdx.x;
    const int wid = tid >> 5, lane = tid & 31;
    const int lr = lane >> 2, lc = lane & 3;
    const int nt = blockIdx.x, mt = blockIdx.y;
    const int wm = (wid & 1) * 64, wn = (wid >> 1) * 32;

    if (tid < BN2) {
        const int n = nt * BN2 + tid;
        const float inv = rsqrtf(var[n] + EPSV);
        const float sc = inv * gamma[n];
        s_scale[tid] = sc;
        s_shift[tid] = beta[n] - mean[n] * sc;
    }

    float c[4][4][4];
    #pragma unroll
    for (int mi = 0; mi < 4; mi++)
        #pragma unroll
        for (int ni = 0; ni < 4; ni++)
            #pragma unroll
            for (int j = 0; j < 4; j++) c[mi][ni][j] = 0.f;

    const float* Ab = A  + (size_t)(mt * BM) * Kdim;
    const float* Bb = Bw + (size_t)(nt * BN2) * Kdim;
    const uint32_t smbase = smem_u32(sm + P_TILES);
    const int NC = Kdim / BK;

    auto load_stage = [&](int s, int kc) {
        const uint32_t stage = smbase + (uint32_t)(s * P_STAGE) * 4u;
        #pragma unroll
        for (int i = 0; i < 2; i++) {          // A: 128 rows x 8 float4
            const int idx = tid + i * 512, r = idx >> 3, q = idx & 7;
            cp_async16(stage + (uint32_t)(r * ASTR + q * 4) * 4u,
                       Ab + (size_t)r * Kdim + kc + q * 4);
        }
        #pragma unroll
        for (int i = 0; i < 4; i++) {          // B: 256 rows x 8 float4
            const int idx = tid + i * 512, r = idx >> 3, q = idx & 7;
            cp_async16(stage + (uint32_t)(P_BOFF + r * ASTR + q * 4) * 4u,
                       Bb + (size_t)r * Kdim + kc + q * 4);
        }
    };

    load_stage(0, 0);
    CP_COMMIT();

    for (int it = 0; it < NC; ++it) {
        const int s = it & 1;
        if (it + 1 < NC) {
            load_stage(s ^ 1, (it + 1) * BK);
            CP_COMMIT();
            CP_WAIT(1);
        } else {
            CP_WAIT(0);
        }
        __syncthreads();

        const float* As = sm + P_TILES + s * P_STAGE;
        const float* Bs = As + P_BOFF;
        #pragma unroll
        for (int kk = 0; kk < BK; kk += 8) {
            uint32_t af[4][4], bf[4][2];
            #pragma unroll
            for (int t = 0; t < 4; t++) {
                const int m0 = wm + t * 16;
                af[t][0] = f2tf(As[(m0 + lr)     * ASTR + kk + lc]);
                af[t][1] = f2tf(As[(m0 + lr + 8) * ASTR + kk + lc]);
                af[t][2] = f2tf(As[(m0 + lr)     * ASTR + kk + lc + 4]);
                af[t][3] = f2tf(As[(m0 + lr + 8) * ASTR + kk + lc + 4]);
            }
            #pragma unroll
            for (int t = 0; t < 4; t++) {
                const int n0 = wn + t * 8;
                bf[t][0] = f2tf(Bs[(n0 + lr) * ASTR + kk + lc]);
                bf[t][1] = f2tf(Bs[(n0 + lr) * ASTR + kk + lc + 4]);
            }
            #pragma unroll
            for (int mi = 0; mi < 4; mi++)
                #pragma unroll
                for (int ni = 0; ni < 4; ni++)
                    mma_tf32(c[mi][ni], af[mi], bf[ni]);
        }
        __syncthreads();
    }

    // ---------------- epilogue: two 128-column passes through Cs ----------------
    const int P0 = mt * BM, b = P0 >> 12, p0 = P0 & 4095;
    #pragma unroll
    for (int hp = 0; hp < 2; hp++) {
        if ((wid >> 3) == hp) {                // warps owning this n-half
            const int wnl = wn & 127;
            #pragma unroll
            for (int mi = 0; mi < 4; mi++) {
                #pragma unroll
                for (int ni = 0; ni < 4; ni++) {
                    const int m0 = wm + mi * 16, n0 = wnl + ni * 8;
                    Cs[(m0 + lr)     * CSTR + n0 + 2 * lc]     = c[mi][ni][0];
                    Cs[(m0 + lr)     * CSTR + n0 + 2 * lc + 1] = c[mi][ni][1];
                    Cs[(m0 + lr + 8) * CSTR + n0 + 2 * lc]     = c[mi][ni][2];
                    Cs[(m0 + lr + 8) * CSTR + n0 + 2 * lc + 1] = c[mi][ni][3];
                }
            }
        }
        __syncthreads();
        if (EPI != 3) {
            #pragma unroll
            for (int i = 0; i < 32; i++) {
                const int n = tid & 127;
                const int p = i * 4 + (tid >> 7);
                const int nl = hp * 128 + n;
                const float v = fmaxf(Cs[p * CSTR + n] * s_scale[nl] + s_shift[nl], 0.f);
                outNHWC[(size_t)(P0 + p) * PLANES + nt * BN2 + nl] = v;
            }
        } else {
            #pragma unroll
            for (int i = 0; i < 32; i++) {
                const int n = i * 4 + (tid >> 7);
                const int p = tid & 127;
                const int nl = hp * 128 + n;
                float v = Cs[p * CSTR + n] * s_scale[nl] + s_shift[nl];
                const size_t o = ((size_t)b * Cout + nt * BN2 + nl) * NPIX + p0 + p;
                v += resid[o];
                outNCHW[o] = fmaxf(v, 0.f);
            }
        }
        __syncthreads();
    }
}

// ======================= deform GEMM: inline bilinear im2col, 128x256, 512 thr =======================
__global__ __launch_bounds__(512, 1)
void gemm_deform(const float* __restrict__ out1,   // NHWC [16384][256]
                 const float* __restrict__ off,    // [b][18][4096]
                 const float* __restrict__ Bw,     // w2r [256][2304]
                 float* __restrict__ outNHWC,
                 const float* __restrict__ bias,
                 const float* __restrict__ gamma, const float* __restrict__ beta,
                 const float* __restrict__ mean, const float* __restrict__ var)
{
    extern __shared__ float sm[];
    float* s_scale = sm + D_SCALE;
    float* s_shift = sm + D_SHIFT;
    float* As = sm + D_A;
    float* Bs = sm + D_B;
    float* Cs = sm + D_A;                     // alias post-loop

    const int tid = threadIdx.x;
    const int wid = tid >> 5, lane = tid & 31;
    const int lr = lane >> 2, lc = lane & 3;
    const int mt = blockIdx.x;
    const int wm = (wid & 1) * 64, wn = (wid >> 1) * 32;
    const int Kdim = PLANES * 9;

    if (tid < BN2) {
        const int n = tid;
        const float inv = rsqrtf(var[n] + EPSV);
        const float sc = inv * gamma[n];
        s_scale[tid] = sc;
        s_shift[tid] = beta[n] - mean[n] * sc + bias[n] * sc;
    }

    float c[4][4][4];
    #pragma unroll
    for (int mi = 0; mi < 4; mi++)
        #pragma unroll
        for (int ni = 0; ni < 4; ni++)
            #pragma unroll
            for (int j = 0; j < 4; j++) c[mi][ni][j] = 0.f;

    const int P0 = mt * BM, b = P0 >> 12;
    const size_t rb = (size_t)(b << 12);
    const float* offb = off + (size_t)b * 18 * NPIX;
    const uint32_t* As32 = (const uint32_t*)As;
    const uint32_t* Bs32 = (const uint32_t*)Bs;

    for (int kc = 0; kc < Kdim; kc += BK) {
        const int k  = kc >> 8;           // tap constant over chunk (256 % 32 == 0)
        const int c0 = kc & 255;
        const int ky = (k / 3) * 2 - 2, kx = (k % 3) * 2 - 2;
        __syncthreads();
        #pragma unroll
        for (int i = 0; i < 2; i++) {     // A: 128 rows x 8 float4, bilinear gather
            const int idx = tid + i * 512, r = idx >> 3, q = idx & 7;
            const int p = (P0 + r) & 4095, h = p >> 6, w = p & 63;
            const float oy = offb[(2 * k)     * NPIX + p];
            const float ox = offb[(2 * k + 1) * NPIX + p];
            const float py = (float)(ky + h) + oy;
            const float px = (float)(kx + w) + ox;
            const float y0f = floorf(py), x0f = floorf(px);
            const float wy = py - y0f, wx = px - x0f;
            const int y0 = (int)y0f, x0 = (int)x0f, y1 = y0 + 1, x1 = x0 + 1;
            const float vy0 = (y0 >= 0 && y0 < 64) ? 1.f : 0.f;
            const float vy1 = (y1 >= 0 && y1 < 64) ? 1.f : 0.f;
            const float vx0 = (x0 >= 0 && x0 < 64) ? 1.f : 0.f;
            const float vx1 = (x1 >= 0 && x1 < 64) ? 1.f : 0.f;
            const int cy0 = min(max(y0, 0), 63), cy1 = min(max(y1, 0), 63);
            const int cx0 = min(max(x0, 0), 63), cx1 = min(max(x1, 0), 63);
            const float w00 = (1.f - wy) * (1.f - wx) * vy0 * vx0;
            const float w01 = (1.f - wy) * wx         * vy0 * vx1;
            const float w10 = wy         * (1.f - wx) * vy1 * vx0;
            const float w11 = wy         * wx         * vy1 * vx1;
            const int cc = c0 + q * 4;
            const float4 a0 = *(const float4*)(out1 + (rb + cy0 * 64 + cx0) * PLANES + cc);
            const float4 a1 = *(const float4*)(out1 + (rb + cy0 * 64 + cx1) * PLANES + cc);
            const float4 a2 = *(const float4*)(out1 + (rb + cy1 * 64 + cx0) * PLANES + cc);
            const float4 a3 = *(const float4*)(out1 + (rb + cy1 * 64 + cx1) * PLANES + cc);
            uint4 ua;
            ua.x = f2tf(w00 * a0.x + w01 * a1.x + w10 * a2.x + w11 * a3.x);
            ua.y = f2tf(w00 * a0.y + w01 * a1.y + w10 * a2.y + w11 * a3.y);
            ua.z = f2tf(w00 * a0.z + w01 * a1.z + w10 * a2.z + w11 * a3.z);
            ua.w = f2tf(w00 * a0.w + w01 * a1.w + w10 * a2.w + w11 * a3.w);
            *(uint4*)(As + r * ASTR + q * 4) = ua;
        }
        #pragma unroll
        for (int i = 0; i < 4; i++) {     // B: 256 rows x 8 float4
            const int idx = tid + i * 512, r = idx >> 3, q = idx & 7;
            float4 vb = *(const float4*)(Bw + (size_t)r * Kdim + kc + q * 4);
            uint4 ub; ub.x = f2tf(vb.x); ub.y = f2tf(vb.y); ub.z = f2tf(vb.z); ub.w = f2tf(vb.w);
            *(uint4*)(Bs + r * ASTR + q * 4) = ub;
        }
        __syncthreads();

        #pragma unroll
        for (int kk = 0; kk < BK; kk += 8) {
            uint32_t af[4][4], bf[4][2];
            #pragma unroll
            for (int t = 0; t < 4; t++) {
                const int m0 = wm + t * 16;
                af[t][0] = As32[(m0 + lr)     * ASTR + kk + lc];
                af[t][1] = As32[(m0 + lr + 8) * ASTR + kk + lc];
                af[t][2] = As32[(m0 + lr)     * ASTR + kk + lc + 4];
                af[t][3] = As32[(m0 + lr + 8) * ASTR + kk + lc + 4];
            }
            #pragma unroll
            for (int t = 0; t < 4; t++) {
                const int n0 = wn + t * 8;
                bf[t][0] = Bs32[(n0 + lr) * ASTR + kk + lc];
                bf[t][1] = Bs32[(n0 + lr) * ASTR + kk + lc + 4];
            }
            #pragma unroll
            for (int mi = 0; mi < 4; mi++)
                #pragma unroll
                for (int ni = 0; ni < 4; ni++)
                    mma_tf32(c[mi][ni], af[mi], bf[ni]);
        }
    }

    // two-pass epilogue (NHWC, full 256 cols)
    #pragma unroll
    for (int hp = 0; hp < 2; hp++) {
        __syncthreads();
        if ((wid >> 3) == hp) {
            const int wnl = wn & 127;
            #pragma unroll
            for (int mi = 0; mi < 4; mi++) {
                #pragma unroll
                for (int ni = 0; ni < 4; ni++) {
                    const int m0 = wm + mi * 16, n0 = wnl + ni * 8;
                    Cs[(m0 + lr)     * CSTR + n0 + 2 * lc]     = c[mi][ni][0];
                    Cs[(m0 + lr)     * CSTR + n0 + 2 * lc + 1] = c[mi][ni][1];
                    Cs[(m0 + lr + 8) * CSTR + n0 + 2 * lc]     = c[mi][ni][2];
                    Cs[(m0 + lr + 8) * CSTR + n0 + 2 * lc + 1] = c[mi][ni][3];
                }
            }
        }
        __syncthreads();
        #pragma unroll
        for (int i = 0; i < 32; i++) {
            const int n = tid & 127;
            const int p = i * 4 + (tid >> 7);
            const int nl = hp * 128 + n;
            const float v = fmaxf(Cs[p * CSTR + n] * s_scale[nl] + s_shift[nl], 0.f);
            outNHWC[(size_t)(P0 + p) * PLANES + nl] = v;
        }
    }
}

// ======================= offset GEMM: shifted-window A loader, N=32 (18 used) =======================
__global__ __launch_bounds__(256)
void gemm_off(const float* __restrict__ out1,     // NHWC
              const float* __restrict__ Bw,       // woffp [32][2304]
              const float* __restrict__ boff,
              float* __restrict__ off)
{
    __shared__ float As[BM * ASTR];
    __shared__ float Bs[32 * ASTR];
    float* Cs = As;                                // alias: 128*33 = 4224 < 4608

    const int tid = threadIdx.x;
    const int wid = tid >> 5, lane = tid & 31;
    const int lr = lane >> 2, lc = lane & 3;
    const int mt = blockIdx.x;
    const int wm = (wid & 1) * 64, wn = (wid >> 1) * 8;
    const int Kdim = PLANES * 9;

    float c[4][4];
    #pragma unroll
    for (int mi = 0; mi < 4; mi++)
        #pragma unroll
        for (int j = 0; j < 4; j++) c[mi][j] = 0.f;

    const int P0 = mt * BM, b = P0 >> 12;
    const size_t rb = (size_t)(b << 12);
    const uint32_t* As32 = (const uint32_t*)As;
    const uint32_t* Bs32 = (const uint32_t*)Bs;

    for (int kc = 0; kc < Kdim; kc += BK) {
        const int k  = kc >> 8;
        const int c0 = kc & 255;
        const int ky = (k / 3) * 2 - 2, kx = (k % 3) * 2 - 2;
        __syncthreads();
        #pragma unroll
        for (int i = 0; i < 4; i++) {
            const int u = tid + i * 256, r = u >> 3, q = u & 7;
            const int p = (P0 + r) & 4095, h = p >> 6, w = p & 63;
            const int yy = h + ky, xx = w + kx;
            uint4 ua;
            if (yy >= 0 && yy < 64 && xx >= 0 && xx < 64) {
                const float4 v = *(const float4*)(out1 + (rb + yy * 64 + xx) * PLANES + c0 + q * 4);
                ua.x = f2tf(v.x); ua.y = f2tf(v.y); ua.z = f2tf(v.z); ua.w = f2tf(v.w);
            } else {
                ua.x = ua.y = ua.z = ua.w = 0u;
            }
            *(uint4*)(As + r * ASTR + q * 4) = ua;
        }
        {
            const int r = tid >> 3, q = tid & 7;
            float4 vb = *(const float4*)(Bw + (size_t)r * Kdim + kc + q * 4);
            uint4 ub; ub.x = f2tf(vb.x); ub.y = f2tf(vb.y); ub.z = f2tf(vb.z); ub.w = f2tf(vb.w);
            *(uint4*)(Bs + r * ASTR + q * 4) = ub;
        }
        __syncthreads();

        #pragma unroll
        for (int kk = 0; kk < BK; kk += 8) {
            uint32_t af[4][4], bf[2];
            #pragma unroll
            for (int t = 0; t < 4; t++) {
                const int m0 = wm + t * 16;
                af[t][0] = As32[(m0 + lr)     * ASTR + kk + lc];
                af[t][1] = As32[(m0 + lr + 8) * ASTR + kk + lc];
                af[t][2] = As32[(m0 + lr)     * ASTR + kk + lc + 4];
                af[t][3] = As32[(m0 + lr + 8) * ASTR + kk + lc + 4];
            }
            bf[0] = Bs32[(wn + lr) * ASTR + kk + lc];
            bf[1] = Bs32[(wn + lr) * ASTR + kk + lc + 4];
            #pragma unroll
            for (int mi = 0; mi < 4; mi++)
                mma_tf32(c[mi], af[mi], bf);
        }
    }

    __syncthreads();
    #pragma unroll
    for (int mi = 0; mi < 4; mi++) {
        const int m0 = wm + mi * 16;
        Cs[(m0 + lr)     * 33 + wn + 2 * lc]     = c[mi][0];
        Cs[(m0 + lr)     * 33 + wn + 2 * lc + 1] = c[mi][1];
        Cs[(m0 + lr + 8) * 33 + wn + 2 * lc]     = c[mi][2];
        Cs[(m0 + lr + 8) * 33 + wn + 2 * lc + 1] = c[mi][3];
    }
    __syncthreads();

    const int p0 = P0 & 4095;
    #pragma unroll
    for (int i = 0; i < 9; i++) {
        const int o = i * 2 + (tid >> 7);
        const int p = tid & 127;
        off[((size_t)b * 18 + o) * NPIX + p0 + p] = Cs[p * 33 + o] + boff[o];
    }
}

// ======================= transpose x: [b][1024][4096] -> xT [b*4096+p][1024] =======================
__global__ __launch_bounds__(256)
void transpose_k(const float* __restrict__ x, float* __restrict__ xT)
{
    __shared__ float t[32][33];
    const int b = blockIdx.z;
    const int p0 = blockIdx.x * 32, c0 = blockIdx.y * 32;
    const float* in = x + (size_t)b * CIN * NPIX;
    float* out = xT + (size_t)b * NPIX * CIN;
    const int tx = threadIdx.x & 31, ty = threadIdx.x >> 5;
    #pragma unroll
    for (int i = 0; i < 32; i += 8)
        t[ty + i][tx] = in[(size_t)(c0 + ty + i) * NPIX + p0 + tx];
    __syncthreads();
    #pragma unroll
    for (int i = 0; i < 32; i += 8)
        out[(size_t)(p0 + ty + i) * CIN + c0 + tx] = t[tx][ty + i];
}

// ======================= weight reshuffles =======================
__global__ __launch_bounds__(256)
void w2r_k(const float* __restrict__ w2, float* __restrict__ w2r)
{
    const int idx = blockIdx.x * 256 + threadIdx.x;
    const int o = idx / 2304, rr = idx % 2304;
    const int k = rr >> 8, cc = rr & 255;
    w2r[idx] = w2[((size_t)o * 256 + cc) * 9 + k];
}
__global__ __launch_bounds__(256)
void woffr_k(const float* __restrict__ woff, float* __restrict__ woffp)
{
    const int idx = blockIdx.x * 256 + threadIdx.x;
    const int o = idx / 2304, rr = idx % 2304;
    const int k = rr >> 8, cc = rr & 255;
    woffp[idx] = (o < 18) ? woff[((size_t)o * 256 + cc) * 9 + k] : 0.f;
}

// ======================= launch =======================
extern "C" void kernel_launch(void* const* d_in, const int* in_sizes, int n_in,
                              void* d_out, int out_size)
{
    const float* x      = (const float*)d_in[0];
    const float* w1     = (const float*)d_in[1];
    const float* gamma1 = (const float*)d_in[2];
    const float* beta1  = (const float*)d_in[3];
    const float* mean1  = (const float*)d_in[4];
    const float* var1   = (const float*)d_in[5];
    const float* woff   = (const float*)d_in[6];
    const float* boff   = (const float*)d_in[7];
    const float* w2     = (const float*)d_in[8];
    const float* bconv2 = (const float*)d_in[9];
    const float* gamma2 = (const float*)d_in[10];
    const float* beta2  = (const float*)d_in[11];
    const float* mean2  = (const float*)d_in[12];
    const float* var2   = (const float*)d_in[13];
    const float* w3     = (const float*)d_in[14];
    const float* gamma3 = (const float*)d_in[15];
    const float* beta3  = (const float*)d_in[16];
    const float* mean3  = (const float*)d_in[17];
    const float* var3   = (const float*)d_in[18];
    float* out = (float*)d_out;

    float *p_xT, *p_o1h, *p_off, *p_out2, *p_w2r, *p_woffp;
    cudaGetSymbolAddress((void**)&p_xT,    g_xT);
    cudaGetSymbolAddress((void**)&p_o1h,   g_out1_nhwc);
    cudaGetSymbolAddress((void**)&p_off,   g_off);
    cudaGetSymbolAddress((void**)&p_out2,  g_out2);
    cudaGetSymbolAddress((void**)&p_w2r,   g_w2r);
    cudaGetSymbolAddress((void**)&p_woffp, g_woffp);

    cudaFuncSetAttribute(gemm_mma<1>, cudaFuncAttributeMaxDynamicSharedMemorySize, P_BYTES);
    cudaFuncSetAttribute(gemm_mma<3>, cudaFuncAttributeMaxDynamicSharedMemorySize, P_BYTES);
    cudaFuncSetAttribute(gemm_deform, cudaFuncAttributeMaxDynamicSharedMemorySize, D_BYTES);
    cudaFuncSetAttribute(gemm_mma<1>, cudaFuncAttributePreferredSharedMemoryCarveout, 100);
    cudaFuncSetAttribute(gemm_mma<3>, cudaFuncAttributePreferredSharedMemoryCarveout, 100);
    cudaFuncSetAttribute(gemm_deform, cudaFuncAttributePreferredSharedMemoryCarveout, 100);

    // independent prep
    transpose_k<<<dim3(NPIX / 32, CIN / 32, BATCH), 256>>>(x, p_xT);
    w2r_k<<<2304, 256>>>(w2, p_w2r);
    woffr_k<<<288, 256>>>(woff, p_woffp);

    // 1) conv1: [16384,1024] x [256,1024]^T -> out1 NHWC, BN1+ReLU  (grid 128 = 1 wave)
    gemm_mma<1><<<dim3(PLANES / BN2, MTOT / BM), 512, P_BYTES>>>(
        p_xT, w1, CIN, p_o1h, nullptr,
        gamma1, beta1, mean1, var1, nullptr, PLANES);

    // 2) offset predictor as GEMM (shifted-window gather A)
    gemm_off<<<MTOT / BM, 256>>>(p_o1h, p_woffp, boff, p_off);

    // 3) deform GEMM with inline bilinear im2col + bias + BN2 + ReLU -> out2 NHWC
    gemm_deform<<<MTOT / BM, 512, D_BYTES>>>(
        p_o1h, p_off, p_w2r, p_out2, bconv2,
        gamma2, beta2, mean2, var2);

    // 4) conv3: [16384,256] x [1024,256]^T, BN3 + residual + ReLU -> out NCHW
    gemm_mma<3><<<dim3(CIN / BN2, MTOT / BM), 512, P_BYTES>>>(
        p_out2, w3, PLANES, nullptr, out,
        gamma3, beta3, mean3, var3, x, CIN);
}

// round 17
// speedup vs baseline: 3.0099x; 1.0443x over previous
#include <cuda_runtime.h>
#include <cstdint>
#include <cstddef>

#define BATCH   4
#define CIN     1024
#define NPIX    4096
#define MTOT    (BATCH * NPIX)      // 16384 pixels total
#define PLANES  256
#define EPSV    1e-5f

// ---------------- scratch (device globals: allocation-guard safe) ----------------
__device__ float g_xT       [(size_t)MTOT * CIN];          // 64 MB  x transposed [P][C] (tf32-rounded)
__device__ float g_out1_nhwc[(size_t)MTOT * PLANES];       // 16 MB  [P][256] (tf32-rounded)
__device__ float g_off      [(size_t)BATCH * 18 * NPIX];   // 1.2 MB
__device__ float g_out2     [(size_t)MTOT * PLANES];       // 16 MB  [P][256] (tf32-rounded)
__device__ float g_w2r      [(size_t)PLANES * PLANES * 9]; // 2.3 MB [o][k*256+c] (rounded)
__device__ float g_woffp    [(size_t)32 * PLANES * 9];     // 0.3 MB [o(pad32)][k*256+c] (rounded)
__device__ float g_w1r      [(size_t)PLANES * CIN];        // 1 MB   rounded w1
__device__ float g_w3r      [(size_t)CIN * PLANES];        // 1 MB   rounded w3

// ---------------- helpers ----------------
__device__ __forceinline__ uint32_t f2tf(float f) {   // round-to-nearest tf32
    uint32_t u;
    asm("cvt.rna.tf32.f32 %0, %1;" : "=r"(u) : "f"(f));
    return u;
}
__device__ __forceinline__ void mma_tf32(float* c, const uint32_t* a, const uint32_t* b) {
    asm volatile(
        "mma.sync.aligned.m16n8k8.row.col.f32.tf32.tf32.f32 "
        "{%0,%1,%2,%3}, {%4,%5,%6,%7}, {%8,%9}, {%0,%1,%2,%3};"
        : "+f"(c[0]), "+f"(c[1]), "+f"(c[2]), "+f"(c[3])
        : "r"(a[0]), "r"(a[1]), "r"(a[2]), "r"(a[3]), "r"(b[0]), "r"(b[1]));
}
__device__ __forceinline__ void ldsm_x4(uint32_t* r, uint32_t addr) {
    asm volatile("ldmatrix.sync.aligned.m8n8.x4.shared.b16 {%0,%1,%2,%3}, [%4];"
                 : "=r"(r[0]), "=r"(r[1]), "=r"(r[2]), "=r"(r[3]) : "r"(addr));
}
__device__ __forceinline__ uint32_t smem_u32(const void* p) {
    uint32_t a;
    asm("{ .reg .u64 t; cvta.to.shared.u64 t, %1; cvt.u32.u64 %0, t; }" : "=r"(a) : "l"(p));
    return a;
}
__device__ __forceinline__ void cp_async16(uint32_t dst, const void* src) {
    asm volatile("cp.async.cg.shared.global [%0], [%1], 16;" :: "r"(dst), "l"(src));
}
#define CP_COMMIT()  asm volatile("cp.async.commit_group;" ::: "memory")
#define CP_WAIT(n)   asm volatile("cp.async.wait_group %0;" :: "n"(n) : "memory")

#define BM   128
#define BN2  256                 // wide CTA tile: 128x256, 512 threads, 16 warps (2M x 8N)
#define BK   32
#define ASTR 36                  // padded K-stride (144B = 16 mod 128 -> ldmatrix conflict-free)
#define CSTR 133                 // padded N-stride for C staging

// ======== plain GEMM smem (double-buffered staging, 512 thr) ========
#define P_SCALE   0
#define P_SHIFT   256
#define P_TILES   512
#define P_STAGE   13824                      // A(128*36) + B(256*36)
#define P_BOFF    4608
#define P_FLOATS  (P_TILES + 2 * P_STAGE)    // 28160 floats
#define P_BYTES   (P_FLOATS * 4)             // 112640 B

// ======== deform GEMM smem (single-buffered, 512 thr) ========
#define D_SCALE   0
#define D_SHIFT   256
#define D_A       512
#define D_B       (D_A + BM * ASTR)
#define D_FLOATS  (D_A + BM * CSTR)
#define D_BYTES   (D_FLOATS * 4)             // 70144 B

// per-lane ldmatrix address offsets (in floats), validated mapping:
//  A x4: mats = (m0,kk),(m0+8,kk),(m0,kk+4),(m0+8,kk+4); thread t -> mat t>>3, row t&7
#define AOFF(lane) ((((lane) & 7) + (((lane) >> 3) & 1) * 8) * ASTR + ((lane) >> 4) * 4)
//  B x4: mats = (n0,kk),(n0,kk+4),(n0+8,kk),(n0+8,kk+4)
#define BOFF(lane) ((((lane) & 7) + ((lane) >> 4) * 8) * ASTR + (((lane) >> 3) & 1) * 4)

// ======================= plain tf32 GEMM, cp.async + ldmatrix, 128x256 =======================
// EPI 1: relu(BN(acc)) tf32-rounded -> NHWC   (conv1)
// EPI 3: relu(BN(acc) + resid)      -> NCHW   (conv3, Cout=1024)
template<int EPI>
__global__ __launch_bounds__(512, 1)
void gemm_mma(const float* __restrict__ A, const float* __restrict__ Bw,
              int Kdim,
              float* __restrict__ outNHWC, float* __restrict__ outNCHW,
              const float* __restrict__ gamma, const float* __restrict__ beta,
              const float* __restrict__ mean, const float* __restrict__ var,
              const float* __restrict__ resid, int Cout)
{
    extern __shared__ float sm[];
    float* s_scale = sm + P_SCALE;
    float* s_shift = sm + P_SHIFT;
    float* Cs = sm + P_TILES;

    const int tid = threadIdx.x;
    const int wid = tid >> 5, lane = tid & 31;
    const int lr = lane >> 2, lc = lane & 3;
    const int nt = blockIdx.x, mt = blockIdx.y;
    const int wm = (wid & 1) * 64, wn = (wid >> 1) * 32;

    if (tid < BN2) {
        const int n = nt * BN2 + tid;
        const float inv = rsqrtf(var[n] + EPSV);
        const float sc = inv * gamma[n];
        s_scale[tid] = sc;
        s_shift[tid] = beta[n] - mean[n] * sc;
    }

    float c[4][4][4];
    #pragma unroll
    for (int mi = 0; mi < 4; mi++)
        #pragma unroll
        for (int ni = 0; ni < 4; ni++)
            #pragma unroll
            for (int j = 0; j < 4; j++) c[mi][ni][j] = 0.f;

    const float* Ab = A  + (size_t)(mt * BM) * Kdim;
    const float* Bb = Bw + (size_t)(nt * BN2) * Kdim;
    const uint32_t smbase = smem_u32(sm + P_TILES);
    const int NC = Kdim / BK;
    const uint32_t aoff = AOFF(lane), boff = BOFF(lane);

    auto load_stage = [&](int s, int kc) {
        const uint32_t stage = smbase + (uint32_t)(s * P_STAGE) * 4u;
        #pragma unroll
        for (int i = 0; i < 2; i++) {
            const int idx = tid + i * 512, r = idx >> 3, q = idx & 7;
            cp_async16(stage + (uint32_t)(r * ASTR + q * 4) * 4u,
                       Ab + (size_t)r * Kdim + kc + q * 4);
        }
        #pragma unroll
        for (int i = 0; i < 4; i++) {
            const int idx = tid + i * 512, r = idx >> 3, q = idx & 7;
            cp_async16(stage + (uint32_t)(P_BOFF + r * ASTR + q * 4) * 4u,
                       Bb + (size_t)r * Kdim + kc + q * 4);
        }
    };

    load_stage(0, 0);
    CP_COMMIT();

    for (int it = 0; it < NC; ++it) {
        const int s = it & 1;
        if (it + 1 < NC) {
            load_stage(s ^ 1, (it + 1) * BK);
            CP_COMMIT();
            CP_WAIT(1);
        } else {
            CP_WAIT(0);
        }
        __syncthreads();

        const uint32_t aBase = smbase + (uint32_t)(s * P_STAGE + wm * ASTR + aoff) * 4u;
        const uint32_t bBase = smbase + (uint32_t)(s * P_STAGE + P_BOFF + wn * ASTR + boff) * 4u;
        #pragma unroll
        for (int kk = 0; kk < BK; kk += 8) {
            uint32_t af[4][4], bf[4][2];
            #pragma unroll
            for (int t = 0; t < 4; t++)
                ldsm_x4(af[t], aBase + (uint32_t)(t * 16 * ASTR + kk) * 4u);
            #pragma unroll
            for (int tp = 0; tp < 2; tp++) {
                uint32_t bq[4];
                ldsm_x4(bq, bBase + (uint32_t)(tp * 16 * ASTR + kk) * 4u);
                bf[2 * tp][0] = bq[0]; bf[2 * tp][1] = bq[1];
                bf[2 * tp + 1][0] = bq[2]; bf[2 * tp + 1][1] = bq[3];
            }
            #pragma unroll
            for (int mi = 0; mi < 4; mi++)
                #pragma unroll
                for (int ni = 0; ni < 4; ni++)
                    mma_tf32(c[mi][ni], af[mi], bf[ni]);
        }
        __syncthreads();
    }

    // ---------------- epilogue: two 128-column passes through Cs ----------------
    const int P0 = mt * BM, b = P0 >> 12, p0 = P0 & 4095;
    #pragma unroll
    for (int hp = 0; hp < 2; hp++) {
        if ((wid >> 3) == hp) {
            const int wnl = wn & 127;
            #pragma unroll
            for (int mi = 0; mi < 4; mi++) {
                #pragma unroll
                for (int ni = 0; ni < 4; ni++) {
                    const int m0 = wm + mi * 16, n0 = wnl + ni * 8;
                    Cs[(m0 + lr)     * CSTR + n0 + 2 * lc]     = c[mi][ni][0];
                    Cs[(m0 + lr)     * CSTR + n0 + 2 * lc + 1] = c[mi][ni][1];
                    Cs[(m0 + lr + 8) * CSTR + n0 + 2 * lc]     = c[mi][ni][2];
                    Cs[(m0 + lr + 8) * CSTR + n0 + 2 * lc + 1] = c[mi][ni][3];
                }
            }
        }
        __syncthreads();
        if (EPI != 3) {
            #pragma unroll
            for (int i = 0; i < 32; i++) {
                const int n = tid & 127;
                const int p = i * 4 + (tid >> 7);
                const int nl = hp * 128 + n;
                const float v = fmaxf(Cs[p * CSTR + n] * s_scale[nl] + s_shift[nl], 0.f);
                outNHWC[(size_t)(P0 + p) * PLANES + nt * BN2 + nl] = __uint_as_float(f2tf(v));
            }
        } else {
            #pragma unroll
            for (int i = 0; i < 32; i++) {
                const int n = i * 4 + (tid >> 7);
                const int p = tid & 127;
                const int nl = hp * 128 + n;
                float v = Cs[p * CSTR + n] * s_scale[nl] + s_shift[nl];
                const size_t o = ((size_t)b * Cout + nt * BN2 + nl) * NPIX + p0 + p;
                v += resid[o];
                outNCHW[o] = fmaxf(v, 0.f);
            }
        }
        __syncthreads();
    }
}

// ======================= deform GEMM: inline bilinear im2col, ldmatrix frags =======================
__global__ __launch_bounds__(512, 1)
void gemm_deform(const float* __restrict__ out1,   // NHWC tf32-rounded
                 const float* __restrict__ off,
                 const float* __restrict__ Bw,     // w2r rounded [256][2304]
                 float* __restrict__ outNHWC,
                 const float* __restrict__ bias,
                 const float* __restrict__ gamma, const float* __restrict__ beta,
                 const float* __restrict__ mean, const float* __restrict__ var)
{
    extern __shared__ float sm[];
    float* s_scale = sm + D_SCALE;
    float* s_shift = sm + D_SHIFT;
    float* As = sm + D_A;
    float* Bs = sm + D_B;
    float* Cs = sm + D_A;

    const int tid = threadIdx.x;
    const int wid = tid >> 5, lane = tid & 31;
    const int lr = lane >> 2, lc = lane & 3;
    const int mt = blockIdx.x;
    const int wm = (wid & 1) * 64, wn = (wid >> 1) * 32;
    const int Kdim = PLANES * 9;
    const uint32_t aoff = AOFF(lane), boff = BOFF(lane);

    if (tid < BN2) {
        const int n = tid;
        const float inv = rsqrtf(var[n] + EPSV);
        const float sc = inv * gamma[n];
        s_scale[tid] = sc;
        s_shift[tid] = beta[n] - mean[n] * sc + bias[n] * sc;
    }

    float c[4][4][4];
    #pragma unroll
    for (int mi = 0; mi < 4; mi++)
        #pragma unroll
        for (int ni = 0; ni < 4; ni++)
            #pragma unroll
            for (int j = 0; j < 4; j++) c[mi][ni][j] = 0.f;

    const int P0 = mt * BM, b = P0 >> 12;
    const size_t rb = (size_t)(b << 12);
    const float* offb = off + (size_t)b * 18 * NPIX;
    const uint32_t aBase = smem_u32(As) + (uint32_t)(wm * ASTR + aoff) * 4u;
    const uint32_t bBase = smem_u32(Bs) + (uint32_t)(wn * ASTR + boff) * 4u;

    for (int kc = 0; kc < Kdim; kc += BK) {
        const int k  = kc >> 8;
        const int c0 = kc & 255;
        const int ky = (k / 3) * 2 - 2, kx = (k % 3) * 2 - 2;
        __syncthreads();
        #pragma unroll
        for (int i = 0; i < 2; i++) {     // A: bilinear gather (validated)
            const int idx = tid + i * 512, r = idx >> 3, q = idx & 7;
            const int p = (P0 + r) & 4095, h = p >> 6, w = p & 63;
            const float oy = offb[(2 * k)     * NPIX + p];
            const float ox = offb[(2 * k + 1) * NPIX + p];
            const float py = (float)(ky + h) + oy;
            const float px = (float)(kx + w) + ox;
            const float y0f = floorf(py), x0f = floorf(px);
            const float wy = py - y0f, wx = px - x0f;
            const int y0 = (int)y0f, x0 = (int)x0f, y1 = y0 + 1, x1 = x0 + 1;
            const float vy0 = (y0 >= 0 && y0 < 64) ? 1.f : 0.f;
            const float vy1 = (y1 >= 0 && y1 < 64) ? 1.f : 0.f;
            const float vx0 = (x0 >= 0 && x0 < 64) ? 1.f : 0.f;
            const float vx1 = (x1 >= 0 && x1 < 64) ? 1.f : 0.f;
            const int cy0 = min(max(y0, 0), 63), cy1 = min(max(y1, 0), 63);
            const int cx0 = min(max(x0, 0), 63), cx1 = min(max(x1, 0), 63);
            const float w00 = (1.f - wy) * (1.f - wx) * vy0 * vx0;
            const float w01 = (1.f - wy) * wx         * vy0 * vx1;
            const float w10 = wy         * (1.f - wx) * vy1 * vx0;
            const float w11 = wy         * wx         * vy1 * vx1;
            const int cc = c0 + q * 4;
            const float4 a0 = *(const float4*)(out1 + (rb + cy0 * 64 + cx0) * PLANES + cc);
            const float4 a1 = *(const float4*)(out1 + (rb + cy0 * 64 + cx1) * PLANES + cc);
            const float4 a2 = *(const float4*)(out1 + (rb + cy1 * 64 + cx0) * PLANES + cc);
            const float4 a3 = *(const float4*)(out1 + (rb + cy1 * 64 + cx1) * PLANES + cc);
            uint4 ua;
            ua.x = f2tf(w00 * a0.x + w01 * a1.x + w10 * a2.x + w11 * a3.x);
            ua.y = f2tf(w00 * a0.y + w01 * a1.y + w10 * a2.y + w11 * a3.y);
            ua.z = f2tf(w00 * a0.z + w01 * a1.z + w10 * a2.z + w11 * a3.z);
            ua.w = f2tf(w00 * a0.w + w01 * a1.w + w10 * a2.w + w11 * a3.w);
            *(uint4*)(As + r * ASTR + q * 4) = ua;
        }
        #pragma unroll
        for (int i = 0; i < 4; i++) {     // B: pre-rounded, plain copy
            const int idx = tid + i * 512, r = idx >> 3, q = idx & 7;
            *(float4*)(Bs + r * ASTR + q * 4) =
                *(const float4*)(Bw + (size_t)r * Kdim + kc + q * 4);
        }
        __syncthreads();

        #pragma unroll
        for (int kk = 0; kk < BK; kk += 8) {
            uint32_t af[4][4], bf[4][2];
            #pragma unroll
            for (int t = 0; t < 4; t++)
                ldsm_x4(af[t], aBase + (uint32_t)(t * 16 * ASTR + kk) * 4u);
            #pragma unroll
            for (int tp = 0; tp < 2; tp++) {
                uint32_t bq[4];
                ldsm_x4(bq, bBase + (uint32_t)(tp * 16 * ASTR + kk) * 4u);
                bf[2 * tp][0] = bq[0]; bf[2 * tp][1] = bq[1];
                bf[2 * tp + 1][0] = bq[2]; bf[2 * tp + 1][1] = bq[3];
            }
            #pragma unroll
            for (int mi = 0; mi < 4; mi++)
                #pragma unroll
                for (int ni = 0; ni < 4; ni++)
                    mma_tf32(c[mi][ni], af[mi], bf[ni]);
        }
    }

    // two-pass epilogue (NHWC, tf32-rounded for conv3)
    #pragma unroll
    for (int hp = 0; hp < 2; hp++) {
        __syncthreads();
        if ((wid >> 3) == hp) {
            const int wnl = wn & 127;
            #pragma unroll
            for (int mi = 0; mi < 4; mi++) {
                #pragma unroll
                for (int ni = 0; ni < 4; ni++) {
                    const int m0 = wm + mi * 16, n0 = wnl + ni * 8;
                    Cs[(m0 + lr)     * CSTR + n0 + 2 * lc]     = c[mi][ni][0];
                    Cs[(m0 + lr)     * CSTR + n0 + 2 * lc + 1] = c[mi][ni][1];
                    Cs[(m0 + lr + 8) * CSTR + n0 + 2 * lc]     = c[mi][ni][2];
                    Cs[(m0 + lr + 8) * CSTR + n0 + 2 * lc + 1] = c[mi][ni][3];
                }
            }
        }
        __syncthreads();
        #pragma unroll
        for (int i = 0; i < 32; i++) {
            const int n = tid & 127;
            const int p = i * 4 + (tid >> 7);
            const int nl = hp * 128 + n;
            const float v = fmaxf(Cs[p * CSTR + n] * s_scale[nl] + s_shift[nl], 0.f);
            outNHWC[(size_t)(P0 + p) * PLANES + nl] = __uint_as_float(f2tf(v));
        }
    }
}

// ======================= offset GEMM (unchanged, validated) =======================
__global__ __launch_bounds__(256)
void gemm_off(const float* __restrict__ out1,
              const float* __restrict__ Bw,
              const float* __restrict__ boff,
              float* __restrict__ off)
{
    __shared__ float As[BM * ASTR];
    __shared__ float Bs[32 * ASTR];
    float* Cs = As;

    const int tid = threadIdx.x;
    const int wid = tid >> 5, lane = tid & 31;
    const int lr = lane >> 2, lc = lane & 3;
    const int mt = blockIdx.x;
    const int wm = (wid & 1) * 64, wn = (wid >> 1) * 8;
    const int Kdim = PLANES * 9;

    float c[4][4];
    #pragma unroll
    for (int mi = 0; mi < 4; mi++)
        #pragma unroll
        for (int j = 0; j < 4; j++) c[mi][j] = 0.f;

    const int P0 = mt * BM, b = P0 >> 12;
    const size_t rb = (size_t)(b << 12);
    const uint32_t* As32 = (const uint32_t*)As;
    const uint32_t* Bs32 = (const uint32_t*)Bs;

    for (int kc = 0; kc < Kdim; kc += BK) {
        const int k  = kc >> 8;
        const int c0 = kc & 255;
        const int ky = (k / 3) * 2 - 2, kx = (k % 3) * 2 - 2;
        __syncthreads();
        #pragma unroll
        for (int i = 0; i < 4; i++) {
            const int u = tid + i * 256, r = u >> 3, q = u & 7;
            const int p = (P0 + r) & 4095, h = p >> 6, w = p & 63;
            const int yy = h + ky, xx = w + kx;
            uint4 ua;
            if (yy >= 0 && yy < 64 && xx >= 0 && xx < 64) {
                const float4 v = *(const float4*)(out1 + (rb + yy * 64 + xx) * PLANES + c0 + q * 4);
                ua.x = f2tf(v.x); ua.y = f2tf(v.y); ua.z = f2tf(v.z); ua.w = f2tf(v.w);
            } else {
                ua.x = ua.y = ua.z = ua.w = 0u;
            }
            *(uint4*)(As + r * ASTR + q * 4) = ua;
        }
        {
            const int r = tid >> 3, q = tid & 7;
            float4 vb = *(const float4*)(Bw + (size_t)r * Kdim + kc + q * 4);
            uint4 ub; ub.x = f2tf(vb.x); ub.y = f2tf(vb.y); ub.z = f2tf(vb.z); ub.w = f2tf(vb.w);
            *(uint4*)(Bs + r * ASTR + q * 4) = ub;
        }
        __syncthreads();

        #pragma unroll
        for (int kk = 0; kk < BK; kk += 8) {
            uint32_t af[4][4], bf[2];
            #pragma unroll
            for (int t = 0; t < 4; t++) {
                const int m0 = wm + t * 16;
                af[t][0] = As32[(m0 + lr)     * ASTR + kk + lc];
                af[t][1] = As32[(m0 + lr + 8) * ASTR + kk + lc];
                af[t][2] = As32[(m0 + lr)     * ASTR + kk + lc + 4];
                af[t][3] = As32[(m0 + lr + 8) * ASTR + kk + lc + 4];
            }
            bf[0] = Bs32[(wn + lr) * ASTR + kk + lc];
            bf[1] = Bs32[(wn + lr) * ASTR + kk + lc + 4];
            #pragma unroll
            for (int mi = 0; mi < 4; mi++)
                mma_tf32(c[mi], af[mi], bf);
        }
    }

    __syncthreads();
    #pragma unroll
    for (int mi = 0; mi < 4; mi++) {
        const int m0 = wm + mi * 16;
        Cs[(m0 + lr)     * 33 + wn + 2 * lc]     = c[mi][0];
        Cs[(m0 + lr)     * 33 + wn + 2 * lc + 1] = c[mi][1];
        Cs[(m0 + lr + 8) * 33 + wn + 2 * lc]     = c[mi][2];
        Cs[(m0 + lr + 8) * 33 + wn + 2 * lc + 1] = c[mi][3];
    }
    __syncthreads();

    const int p0 = P0 & 4095;
    #pragma unroll
    for (int i = 0; i < 9; i++) {
        const int o = i * 2 + (tid >> 7);
        const int p = tid & 127;
        off[((size_t)b * 18 + o) * NPIX + p0 + p] = Cs[p * 33 + o] + boff[o];
    }
}

// ======================= transpose x (tf32-round at write) =======================
__global__ __launch_bounds__(256)
void transpose_k(const float* __restrict__ x, float* __restrict__ xT)
{
    __shared__ float t[32][33];
    const int b = blockIdx.z;
    const int p0 = blockIdx.x * 32, c0 = blockIdx.y * 32;
    const float* in = x + (size_t)b * CIN * NPIX;
    float* out = xT + (size_t)b * NPIX * CIN;
    const int tx = threadIdx.x & 31, ty = threadIdx.x >> 5;
    #pragma unroll
    for (int i = 0; i < 32; i += 8)
        t[ty + i][tx] = in[(size_t)(c0 + ty + i) * NPIX + p0 + tx];
    __syncthreads();
    #pragma unroll
    for (int i = 0; i < 32; i += 8)
        out[(size_t)(p0 + ty + i) * CIN + c0 + tx] = __uint_as_float(f2tf(t[tx][ty + i]));
}

// ======================= weight prep (all tf32-rounded) =======================
__global__ __launch_bounds__(256)
void w2r_k(const float* __restrict__ w2, float* __restrict__ w2r)
{
    const int idx = blockIdx.x * 256 + threadIdx.x;
    const int o = idx / 2304, rr = idx % 2304;
    const int k = rr >> 8, cc = rr & 255;
    w2r[idx] = __uint_as_float(f2tf(w2[((size_t)o * 256 + cc) * 9 + k]));
}
__global__ __launch_bounds__(256)
void woffr_k(const float* __restrict__ woff, float* __restrict__ woffp)
{
    const int idx = blockIdx.x * 256 + threadIdx.x;
    const int o = idx / 2304, rr = idx % 2304;
    const int k = rr >> 8, cc = rr & 255;
    woffp[idx] = (o < 18) ? __uint_as_float(f2tf(woff[((size_t)o * 256 + cc) * 9 + k])) : 0.f;
}
__global__ __launch_bounds__(256)
void roundcpy_k(const float* __restrict__ src, float* __restrict__ dst)
{
    const int i = blockIdx.x * 256 + threadIdx.x;
    dst[i] = __uint_as_float(f2tf(src[i]));
}

// ======================= launch =======================
extern "C" void kernel_launch(void* const* d_in, const int* in_sizes, int n_in,
                              void* d_out, int out_size)
{
    const float* x      = (const float*)d_in[0];
    const float* w1     = (const float*)d_in[1];
    const float* gamma1 = (const float*)d_in[2];
    const float* beta1  = (const float*)d_in[3];
    const float* mean1  = (const float*)d_in[4];
    const float* var1   = (const float*)d_in[5];
    const float* woff   = (const float*)d_in[6];
    const float* boff   = (const float*)d_in[7];
    const float* w2     = (const float*)d_in[8];
    const float* bconv2 = (const float*)d_in[9];
    const float* gamma2 = (const float*)d_in[10];
    const float* beta2  = (const float*)d_in[11];
    const float* mean2  = (const float*)d_in[12];
    const float* var2   = (const float*)d_in[13];
    const float* w3     = (const float*)d_in[14];
    const float* gamma3 = (const float*)d_in[15];
    const float* beta3  = (const float*)d_in[16];
    const float* mean3  = (const float*)d_in[17];
    const float* var3   = (const float*)d_in[18];
    float* out = (float*)d_out;

    float *p_xT, *p_o1h, *p_off, *p_out2, *p_w2r, *p_woffp, *p_w1r, *p_w3r;
    cudaGetSymbolAddress((void**)&p_xT,    g_xT);
    cudaGetSymbolAddress((void**)&p_o1h,   g_out1_nhwc);
    cudaGetSymbolAddress((void**)&p_off,   g_off);
    cudaGetSymbolAddress((void**)&p_out2,  g_out2);
    cudaGetSymbolAddress((void**)&p_w2r,   g_w2r);
    cudaGetSymbolAddress((void**)&p_woffp, g_woffp);
    cudaGetSymbolAddress((void**)&p_w1r,   g_w1r);
    cudaGetSymbolAddress((void**)&p_w3r,   g_w3r);

    cudaFuncSetAttribute(gemm_mma<1>, cudaFuncAttributeMaxDynamicSharedMemorySize, P_BYTES);
    cudaFuncSetAttribute(gemm_mma<3>, cudaFuncAttributeMaxDynamicSharedMemorySize, P_BYTES);
    cudaFuncSetAttribute(gemm_deform, cudaFuncAttributeMaxDynamicSharedMemorySize, D_BYTES);
    cudaFuncSetAttribute(gemm_mma<1>, cudaFuncAttributePreferredSharedMemoryCarveout, 100);
    cudaFuncSetAttribute(gemm_mma<3>, cudaFuncAttributePreferredSharedMemoryCarveout, 100);
    cudaFuncSetAttribute(gemm_deform, cudaFuncAttributePreferredSharedMemoryCarveout, 100);

    // independent prep (all pre-rounded to tf32 values in fp32 storage)
    transpose_k<<<dim3(NPIX / 32, CIN / 32, BATCH), 256>>>(x, p_xT);
    w2r_k<<<2304, 256>>>(w2, p_w2r);
    woffr_k<<<288, 256>>>(woff, p_woffp);
    roundcpy_k<<<(PLANES * CIN) / 256, 256>>>(w1, p_w1r);
    roundcpy_k<<<(CIN * PLANES) / 256, 256>>>(w3, p_w3r);

    // 1) conv1 -> out1 NHWC (tf32-rounded), BN1+ReLU
    gemm_mma<1><<<dim3(PLANES / BN2, MTOT / BM), 512, P_BYTES>>>(
        p_xT, p_w1r, CIN, p_o1h, nullptr,
        gamma1, beta1, mean1, var1, nullptr, PLANES);

    // 2) offset predictor as GEMM
    gemm_off<<<MTOT / BM, 256>>>(p_o1h, p_woffp, boff, p_off);

    // 3) deform GEMM (inline bilinear im2col) -> out2 NHWC (tf32-rounded)
    gemm_deform<<<MTOT / BM, 512, D_BYTES>>>(
        p_o1h, p_off, p_w2r, p_out2, bconv2,
        gamma2, beta2, mean2, var2);

    // 4) conv3 + BN3 + residual + ReLU -> out NCHW
    gemm_mma<3><<<dim3(CIN / BN2, MTOT / BM), 512, P_BYTES>>>(
        p_out2, p_w3r, PLANES, nullptr, out,
        gamma3, beta3, mean3, var3, x, CIN);
}